// round 11
// baseline (speedup 1.0000x reference)
#include <cuda_runtime.h>
#include <cuda_bf16.h>
#include <cuda_fp16.h>
#include <cuda_fp8.h>
#include <cstdint>

// Problem constants
#define BB 2
#define TT 2048
#define CC 1024
#define HH 16
#define DD 64
#define MM (BB * TT)   // 4096 rows

// Residual scale for fp8 planes
#define RSCALE 1024.0f
#define RSCALE_INV 0.0009765625f

// ---------------------------------------------------------------------------
// Device scratch (allocation-free per harness rules)
// ---------------------------------------------------------------------------
// q/k/v bf16 hi/lo (attention operands, unchanged)
__device__ __nv_bfloat16 g_qhi[(size_t)BB * HH * TT * DD];
__device__ __nv_bfloat16 g_qlo[(size_t)BB * HH * TT * DD];
__device__ __nv_bfloat16 g_khi[(size_t)BB * HH * TT * DD];
__device__ __nv_bfloat16 g_klo[(size_t)BB * HH * TT * DD];
__device__ __nv_bfloat16 g_vhi[(size_t)BB * HH * TT * DD];
__device__ __nv_bfloat16 g_vlo[(size_t)BB * HH * TT * DD];
// GEMM A/B operands: bf16 main + fp8 value + fp8 residual (x RSCALE)
__device__ __nv_bfloat16 g_xhi[(size_t)MM * CC];
__device__ uint8_t       g_x8 [(size_t)MM * CC];
__device__ uint8_t       g_x8r[(size_t)MM * CC];
__device__ __nv_bfloat16 g_wahi[(size_t)3 * CC * CC];    // W_attn^T [N][K]
__device__ uint8_t       g_wa8 [(size_t)3 * CC * CC];
__device__ uint8_t       g_wa8r[(size_t)3 * CC * CC];
__device__ __nv_bfloat16 g_wphi[(size_t)CC * CC];        // W_proj^T [N][K]
__device__ uint8_t       g_wp8 [(size_t)CC * CC];
__device__ uint8_t       g_wp8r[(size_t)CC * CC];
__device__ __nv_bfloat16 g_ahi[(size_t)MM * CC];         // attention out
__device__ uint8_t       g_a8 [(size_t)MM * CC];
__device__ uint8_t       g_a8r[(size_t)MM * CC];

// ---------------------------------------------------------------------------
// PTX helpers
// ---------------------------------------------------------------------------
__device__ __forceinline__ uint32_t smem_to_u32(const void* smem_ptr) {
    uint32_t addr;
    asm("{ .reg .u64 tmp; cvta.to.shared.u64 tmp, %1; cvt.u32.u64 %0, tmp; }"
        : "=r"(addr) : "l"(smem_ptr));
    return addr;
}

__device__ __forceinline__ void cpasync16(uint32_t s, const void* g) {
    asm volatile("cp.async.cg.shared.global [%0], [%1], 16;" :: "r"(s), "l"(g) : "memory");
}

#define CP_COMMIT()  asm volatile("cp.async.commit_group;" ::: "memory")
#define CP_WAIT(n)   asm volatile("cp.async.wait_group %0;" :: "n"(n) : "memory")

#define LDSM_X4(r, addr) \
    asm volatile("ldmatrix.sync.aligned.m8n8.x4.shared.b16 {%0,%1,%2,%3}, [%4];" \
        : "=r"((r)[0]), "=r"((r)[1]), "=r"((r)[2]), "=r"((r)[3]) : "r"(addr))

#define LDSM_X4_T(r, addr) \
    asm volatile("ldmatrix.sync.aligned.m8n8.x4.trans.shared.b16 {%0,%1,%2,%3}, [%4];" \
        : "=r"((r)[0]), "=r"((r)[1]), "=r"((r)[2]), "=r"((r)[3]) : "r"(addr))

#define MMA_BF16(c, a, b0, b1) \
    asm volatile("mma.sync.aligned.m16n8k16.row.col.f32.bf16.bf16.f32 " \
        "{%0,%1,%2,%3}, {%4,%5,%6,%7}, {%8,%9}, {%0,%1,%2,%3};" \
        : "+f"((c)[0]), "+f"((c)[1]), "+f"((c)[2]), "+f"((c)[3]) \
        : "r"((a)[0]), "r"((a)[1]), "r"((a)[2]), "r"((a)[3]), "r"(b0), "r"(b1))

#define MMA_FP8(c, a, b0, b1) \
    asm volatile("mma.sync.aligned.m16n8k32.row.col.f32.e4m3.e4m3.f32 " \
        "{%0,%1,%2,%3}, {%4,%5,%6,%7}, {%8,%9}, {%0,%1,%2,%3};" \
        : "+f"((c)[0]), "+f"((c)[1]), "+f"((c)[2]), "+f"((c)[3]) \
        : "r"((a)[0]), "r"((a)[1]), "r"((a)[2]), "r"((a)[3]), "r"(b0), "r"(b1))

// fast exp2 on the FMA pipe (no MUFU)
__device__ __forceinline__ float fexp2(float x) {
    x = fmaxf(x, -126.0f);
    float t = x + 12582912.0f;
    float r = t - 12582912.0f;
    float f = x - r;
    int e = (__float_as_int(t) + (127 - 0x400000)) << 23;
    float p = 1.5353361883e-4f;
    p = fmaf(p, f, 1.3398874403e-3f);
    p = fmaf(p, f, 9.6184373577e-3f);
    p = fmaf(p, f, 5.5503324712e-2f);
    p = fmaf(p, f, 2.4022647914e-1f);
    p = fmaf(p, f, 6.9314720286e-1f);
    p = fmaf(p, f, 1.0f);
    return p * __int_as_float(e);
}

// ---------------------------------------------------------------------------
// Precision split helpers
// ---------------------------------------------------------------------------
__device__ __forceinline__ void bf16_split(float v, __nv_bfloat16& h, __nv_bfloat16& l) {
    h = __float2bfloat16(v);
    l = __float2bfloat16(v - __bfloat162float(h));
}

__device__ __forceinline__ uint32_t pack2bf(float x, float y) {
    __nv_bfloat162 v{__float2bfloat16(x), __float2bfloat16(y)};
    return *(uint32_t*)&v;
}

__device__ __forceinline__ uint8_t f2e4m3(float v) {
    return (uint8_t)__nv_cvt_float_to_fp8(v, __NV_SATFINITE, __NV_E4M3);
}

// split v into: bf16 main h, fp8 of v, fp8 of bf16-residual x RSCALE
__device__ __forceinline__ void tri_split(float v, __nv_bfloat16& h,
                                          uint8_t& q8, uint8_t& q8r) {
    h = __float2bfloat16(v);
    float r = v - __bfloat162float(h);
    q8 = f2e4m3(v);
    q8r = f2e4m3(r * RSCALE);
}

__global__ __launch_bounds__(256) void split_x_kernel(const float* __restrict__ x) {
    size_t i = (size_t)blockIdx.x * 256 + threadIdx.x;   // MM*CC/4 float4s
    float4 v = ((const float4*)x)[i];
    __nv_bfloat16 h0, h1, h2, h3;
    uint8_t a0, a1, a2, a3, r0, r1, r2, r3;
    tri_split(v.x, h0, a0, r0); tri_split(v.y, h1, a1, r1);
    tri_split(v.z, h2, a2, r2); tri_split(v.w, h3, a3, r3);
    __nv_bfloat162* ph = (__nv_bfloat162*)(g_xhi + i * 4);
    ph[0] = __nv_bfloat162{h0, h1}; ph[1] = __nv_bfloat162{h2, h3};
    *(uint32_t*)(g_x8 + i * 4)  = (uint32_t)a0 | ((uint32_t)a1 << 8) |
                                  ((uint32_t)a2 << 16) | ((uint32_t)a3 << 24);
    *(uint32_t*)(g_x8r + i * 4) = (uint32_t)r0 | ((uint32_t)r1 << 8) |
                                  ((uint32_t)r2 << 16) | ((uint32_t)r3 << 24);
}

// Transpose + tri-split: W [K=1024][NN] fp32 -> [NN][1024] planes
template <int NN, int WHICH>
__global__ __launch_bounds__(256) void tsplit_w_kernel(const float* __restrict__ W) {
    __shared__ float tile[32][33];
    __nv_bfloat16* Whi = (WHICH == 0) ? g_wahi : g_wphi;
    uint8_t* W8  = (WHICH == 0) ? g_wa8  : g_wp8;
    uint8_t* W8r = (WHICH == 0) ? g_wa8r : g_wp8r;
    const int nb = blockIdx.x * 32;
    const int kb = blockIdx.y * 32;
    const int tx = threadIdx.x, ty = threadIdx.y;
#pragma unroll
    for (int r = 0; r < 4; ++r)
        tile[ty + r * 8][tx] = W[(size_t)(kb + ty + r * 8) * NN + nb + tx];
    __syncthreads();
#pragma unroll
    for (int r = 0; r < 4; ++r) {
        const int n = nb + ty + r * 8;
        const int k = kb + tx;
        float v = tile[tx][ty + r * 8];
        __nv_bfloat16 h; uint8_t q8, q8r;
        tri_split(v, h, q8, q8r);
        Whi[(size_t)n * 1024 + k] = h;
        W8 [(size_t)n * 1024 + k] = q8;
        W8r[(size_t)n * 1024 + k] = q8r;
    }
}

// ---------------------------------------------------------------------------
// Mixed bf16+fp8 tensor-core GEMM: C = A[M,K] @ Wt[N,K]^T + bias
// Main term: bf16 HMMA m16n8k16 (Ah*Bh). Cross terms: e4m3 m16n8k32
// (A8*B8r + A8r*B8), folded once in epilogue by /RSCALE.
// Per k32 chunk: 2 bf16 + 2 fp8 MMAs per (mf,nf) -> 1.5x fewer MMA vs bf16x3.
// CTA tile 128x128, 8 warps 2(m)x4(n), warp tile 64x32.
// SMEM stage 48KB: Ahi@0 A8@8K A8r@16K Bhi@24K B8@32K B8r@40K (64B rows,
// fp8 planes padded to 64B/row; xor swizzle ch^((row>>1)&3)). 3 stages.
// ---------------------------------------------------------------------------
template <int Ndim, int MODE>
__global__ __launch_bounds__(256) void hmma_gemm_kernel(
    const float* __restrict__ bias, float* __restrict__ Out)
{
    extern __shared__ __align__(1024) char smem[];
    const uint32_t sbase = smem_to_u32(smem);
    const int tid = threadIdx.x;
    const int lane = tid & 31;
    const int wid = tid >> 5;
    const int wm = wid >> 2;   // 0..1
    const int wn = wid & 3;    // 0..3
    const int m0 = blockIdx.y * 128;
    const int n0 = blockIdx.x * 128;
    constexpr int KT = 32;
    constexpr int STG = 49152;

    const __nv_bfloat16* Ahi = (MODE == 0) ? g_xhi : g_ahi;
    const uint8_t* A8  = (MODE == 0) ? g_x8  : g_a8;
    const uint8_t* A8r = (MODE == 0) ? g_x8r : g_a8r;
    const __nv_bfloat16* Bhi = (MODE == 0) ? g_wahi : g_wphi;
    const uint8_t* B8  = (MODE == 0) ? g_wa8  : g_wp8;
    const uint8_t* B8r = (MODE == 0) ? g_wa8r : g_wp8r;

    const char* gAh  = (const char*)Ahi + (size_t)m0 * 2048;
    const char* gA8  = (const char*)A8  + (size_t)m0 * 1024;
    const char* gA8r = (const char*)A8r + (size_t)m0 * 1024;
    const char* gBh  = (const char*)Bhi + (size_t)n0 * 2048;
    const char* gB8  = (const char*)B8  + (size_t)n0 * 1024;
    const char* gB8r = (const char*)B8r + (size_t)n0 * 1024;

    float accM[4][4][4], accX[4][4][4];
#pragma unroll
    for (int mf = 0; mf < 4; ++mf)
#pragma unroll
        for (int nf = 0; nf < 4; ++nf)
#pragma unroll
            for (int e = 0; e < 4; ++e) { accM[mf][nf][e] = 0.f; accX[mf][nf][e] = 0.f; }

    auto issue = [&](int c) {
        const uint32_t tb = sbase + (uint32_t)(c % 3) * STG;
        // bf16 planes: 128 rows x 4 chunks = 512 each (2/thread)
#pragma unroll
        for (int i = 0; i < 2; ++i) {
            const int idx = tid + i * 256;
            const int row = idx >> 2;
            const int ch = idx & 3;
            const uint32_t soff = row * 64 + ((ch ^ ((row >> 1) & 3)) << 4);
            const size_t goff = (size_t)row * 2048 + ch * 16 + c * 64;
            cpasync16(tb + 0     + soff, gAh + goff);
            cpasync16(tb + 24576 + soff, gBh + goff);
        }
        // fp8 planes: 128 rows x 2 chunks = 256 each (1/thread)
        {
            const int row = tid >> 1;
            const int ch = tid & 1;
            const uint32_t soff = row * 64 + ((ch ^ ((row >> 1) & 3)) << 4);
            const size_t goff = (size_t)row * 1024 + ch * 16 + c * 32;
            cpasync16(tb + 8192  + soff, gA8  + goff);
            cpasync16(tb + 16384 + soff, gA8r + goff);
            cpasync16(tb + 32768 + soff, gB8  + goff);
            cpasync16(tb + 40960 + soff, gB8r + goff);
        }
        CP_COMMIT();
    };

    issue(0);
    issue(1);

    const int q8l = lane >> 3;
    const int iq = lane & 7;
    const int rowoff_a = ((q8l & 1) << 3) + iq;  // 0..15
    const int khalf = q8l >> 1;                  // 0/1

    for (int c = 0; c < KT; ++c) {
        CP_WAIT(1);
        __syncthreads();
        if (c + 2 < KT) issue(c + 2);

        const uint32_t tb = sbase + (uint32_t)(c % 3) * STG;

        // ---- main bf16 term ----
#pragma unroll
        for (int ks = 0; ks < 2; ++ks) {
            const int cch = ks * 2 + khalf;
            uint32_t ah[4][4];
#pragma unroll
            for (int mf = 0; mf < 4; ++mf) {
                const int row = wm * 64 + mf * 16 + rowoff_a;
                const uint32_t off = row * 64 + ((cch ^ ((row >> 1) & 3)) << 4);
                LDSM_X4(ah[mf], tb + off);
            }
#pragma unroll
            for (int np = 0; np < 2; ++np) {
                const int row = wn * 32 + np * 16 + rowoff_a;
                const uint32_t off = row * 64 + ((cch ^ ((row >> 1) & 3)) << 4);
                uint32_t rh[4];
                LDSM_X4(rh, tb + 24576 + off);
                const int nf0 = 2 * np, nf1 = 2 * np + 1;
#pragma unroll
                for (int mf = 0; mf < 4; ++mf) {
                    MMA_BF16(accM[mf][nf0], ah[mf], rh[0], rh[2]);
                    MMA_BF16(accM[mf][nf1], ah[mf], rh[1], rh[3]);
                }
            }
        }

        // ---- fp8 cross terms (k32 covers whole chunk) ----
        {
            uint32_t a8f[4][4], a8rf[4][4];
#pragma unroll
            for (int mf = 0; mf < 4; ++mf) {
                const int row = wm * 64 + mf * 16 + rowoff_a;
                const uint32_t off = row * 64 + ((khalf ^ ((row >> 1) & 3)) << 4);
                LDSM_X4(a8f[mf], tb + 8192 + off);
                LDSM_X4(a8rf[mf], tb + 16384 + off);
            }
#pragma unroll
            for (int np = 0; np < 2; ++np) {
                const int row = wn * 32 + np * 16 + rowoff_a;
                const uint32_t off = row * 64 + ((khalf ^ ((row >> 1) & 3)) << 4);
                uint32_t r8[4], r8r[4];
                LDSM_X4(r8, tb + 32768 + off);
                LDSM_X4(r8r, tb + 40960 + off);
                const int nf0 = 2 * np, nf1 = 2 * np + 1;
#pragma unroll
                for (int mf = 0; mf < 4; ++mf) {
                    MMA_FP8(accX[mf][nf0], a8f[mf], r8r[0], r8r[2]);
                    MMA_FP8(accX[mf][nf1], a8f[mf], r8r[1], r8r[3]);
                    MMA_FP8(accX[mf][nf0], a8rf[mf], r8[0], r8[2]);
                    MMA_FP8(accX[mf][nf1], a8rf[mf], r8[1], r8[3]);
                }
            }
        }
    }

    // Epilogue: fold cross terms, add bias. Frag map: c0,c1 -> (row g, cols
    // 2t,2t+1); c2,c3 -> row g+8.
    const int g = lane >> 2, t = lane & 3;
#pragma unroll
    for (int mf = 0; mf < 4; ++mf) {
        const int r_lo = m0 + wm * 64 + mf * 16 + g;
#pragma unroll
        for (int nf = 0; nf < 4; ++nf) {
            const int col = n0 + wn * 32 + nf * 8 + 2 * t;
            const float b0 = bias[col], b1 = bias[col + 1];
            float v00 = fmaf(accX[mf][nf][0], RSCALE_INV, accM[mf][nf][0]) + b0;
            float v01 = fmaf(accX[mf][nf][1], RSCALE_INV, accM[mf][nf][1]) + b1;
            float v10 = fmaf(accX[mf][nf][2], RSCALE_INV, accM[mf][nf][2]) + b0;
            float v11 = fmaf(accX[mf][nf][3], RSCALE_INV, accM[mf][nf][3]) + b1;
            if (MODE == 0) {
                const int which = col >> 10;
                const int ci = col & 1023;
                const int hh = ci >> 6;
                const int dd = ci & 63;
                __nv_bfloat16* dh = (which == 0) ? g_qhi : ((which == 1) ? g_khi : g_vhi);
                __nv_bfloat16* dl = (which == 0) ? g_qlo : ((which == 1) ? g_klo : g_vlo);
                __nv_bfloat16 h0, h1, l0, l1;
                const int b_lo = r_lo >> 11, t_lo = r_lo & 2047;
                size_t off = (((size_t)b_lo * HH + hh) * TT + t_lo) * DD + dd;
                bf16_split(v00, h0, l0); bf16_split(v01, h1, l1);
                *(__nv_bfloat162*)(dh + off) = __nv_bfloat162{h0, h1};
                *(__nv_bfloat162*)(dl + off) = __nv_bfloat162{l0, l1};
                const int r_hi = r_lo + 8;
                const int b_hi = r_hi >> 11, t_hi = r_hi & 2047;
                off = (((size_t)b_hi * HH + hh) * TT + t_hi) * DD + dd;
                bf16_split(v10, h0, l0); bf16_split(v11, h1, l1);
                *(__nv_bfloat162*)(dh + off) = __nv_bfloat162{h0, h1};
                *(__nv_bfloat162*)(dl + off) = __nv_bfloat162{l0, l1};
            } else {
                *(float2*)(Out + (size_t)r_lo * Ndim + col) = float2{v00, v01};
                *(float2*)(Out + (size_t)(r_lo + 8) * Ndim + col) = float2{v10, v11};
            }
        }
    }
}

// ---------------------------------------------------------------------------
// Tensor-core flash attention with ALiBi + temperature (math unchanged from
// R8; epilogue now writes bf16 + fp8 planes for the proj GEMM).
// ---------------------------------------------------------------------------
__global__ __launch_bounds__(256) void attn_mma_kernel(const float* __restrict__ temp)
{
    extern __shared__ __align__(1024) char smem[];
    const uint32_t sb = smem_to_u32(smem);
    const int tid = threadIdx.x;
    const int lane = tid & 31;
    const int wid = tid >> 5;
    const int bh = blockIdx.y;
    const int qt = (int)gridDim.x - 1 - blockIdx.x;
    const int b = bh >> 4;
    const int h = bh & 15;

    const float qscale = 0.125f * (1.0f / temp[0]) * 1.44269504088896340736f;
    const float slope = exp2f(-0.5f * (float)(h + 1)) * 1.44269504088896340736f;

    const int q8l = lane >> 3;
    const int iq = lane & 7;
    const int rowoff = ((q8l & 1) << 3) + iq;
    const int khalf = q8l >> 1;
    const int g = lane >> 2, t = lane & 3;

    const char* gQh = (const char*)g_qhi + ((size_t)bh * TT + qt * 128) * 128;
    const char* gQl = (const char*)g_qlo + ((size_t)bh * TT + qt * 128) * 128;
    const char* gKh = (const char*)g_khi + (size_t)bh * TT * 128;
    const char* gKl = (const char*)g_klo + (size_t)bh * TT * 128;
    const char* gVh = (const char*)g_vhi + (size_t)bh * TT * 128;
    const char* gVl = (const char*)g_vlo + (size_t)bh * TT * 128;

    const int nkt = 2 * qt + 2;

#pragma unroll
    for (int i = 0; i < 4; ++i) {
        const int idx = tid + i * 256;
        const int row = idx >> 3;
        const int ch = idx & 7;
        const uint32_t soff = row * 128 + ((ch ^ (row & 7)) << 4);
        const size_t goff = (size_t)row * 128 + ch * 16;
        cpasync16(sb + 0     + soff, gQh + goff);
        cpasync16(sb + 16384 + soff, gQl + goff);
    }
    CP_COMMIT();

    auto issue_kv = [&](int kt) {
        const uint32_t tb = sb + 32768 + (uint32_t)(kt & 1) * 32768;
        const size_t kbase = (size_t)kt * 64 * 128;
#pragma unroll
        for (int i = 0; i < 2; ++i) {
            const int idx = tid + i * 256;
            const int row = idx >> 3;
            const int ch = idx & 7;
            const uint32_t soff = row * 128 + ((ch ^ (row & 7)) << 4);
            const size_t goff = kbase + (size_t)row * 128 + ch * 16;
            cpasync16(tb + 0     + soff, gKh + goff);
            cpasync16(tb + 8192  + soff, gKl + goff);
            cpasync16(tb + 16384 + soff, gVh + goff);
            cpasync16(tb + 24576 + soff, gVl + goff);
        }
        CP_COMMIT();
    };

    issue_kv(0);
    CP_WAIT(1);
    __syncthreads();

    uint32_t qh[4][4], ql[4][4];
#pragma unroll
    for (int ks = 0; ks < 4; ++ks) {
        const int row = wid * 16 + rowoff;
        const int cch = ks * 2 + khalf;
        const uint32_t off = row * 128 + ((cch ^ (row & 7)) << 4);
        LDSM_X4(qh[ks], sb + off);
        LDSM_X4(ql[ks], sb + 16384 + off);
    }

    float oacc[8][4];
#pragma unroll
    for (int nd = 0; nd < 8; ++nd)
#pragma unroll
        for (int e = 0; e < 4; ++e) oacc[nd][e] = 0.f;
    float m0 = -1e30f, m1 = -1e30f, l0 = 0.f, l1 = 0.f;

    const int qrow0 = qt * 128 + wid * 16 + g;
    const int qrow1 = qrow0 + 8;

    for (int kt = 0; kt < nkt; ++kt) {
        if (kt + 1 < nkt) { issue_kv(kt + 1); CP_WAIT(1); }
        else              { CP_WAIT(0); }
        __syncthreads();

        const uint32_t tb = sb + 32768 + (uint32_t)(kt & 1) * 32768;

        float sacc[8][4];
#pragma unroll
        for (int nf = 0; nf < 8; ++nf)
#pragma unroll
            for (int e = 0; e < 4; ++e) sacc[nf][e] = 0.f;

#pragma unroll
        for (int ks = 0; ks < 4; ++ks) {
            const int cch = ks * 2 + khalf;
            uint32_t kbh[8][2], kbl[8][2];
#pragma unroll
            for (int np = 0; np < 4; ++np) {
                const int row = np * 16 + rowoff;
                const uint32_t off = row * 128 + ((cch ^ (row & 7)) << 4);
                uint32_t r[4];
                LDSM_X4(r, tb + off);
                kbh[2 * np][0] = r[0]; kbh[2 * np][1] = r[2];
                kbh[2 * np + 1][0] = r[1]; kbh[2 * np + 1][1] = r[3];
                LDSM_X4(r, tb + 8192 + off);
                kbl[2 * np][0] = r[0]; kbl[2 * np][1] = r[2];
                kbl[2 * np + 1][0] = r[1]; kbl[2 * np + 1][1] = r[3];
            }
#pragma unroll
            for (int nf = 0; nf < 8; ++nf)
                MMA_BF16(sacc[nf], qh[ks], kbh[nf][0], kbh[nf][1]);
#pragma unroll
            for (int nf = 0; nf < 8; ++nf)
                MMA_BF16(sacc[nf], qh[ks], kbl[nf][0], kbl[nf][1]);
#pragma unroll
            for (int nf = 0; nf < 8; ++nf)
                MMA_BF16(sacc[nf], ql[ks], kbh[nf][0], kbh[nf][1]);
        }

        const bool maskt = (kt >= 2 * qt);
        float mx0 = -1e30f, mx1 = -1e30f;
#pragma unroll
        for (int nf = 0; nf < 8; ++nf) {
            const int key = kt * 64 + nf * 8 + 2 * t;
            float s0 = fmaf(sacc[nf][0], qscale, slope * (float)(key - qrow0));
            float s1 = fmaf(sacc[nf][1], qscale, slope * (float)(key + 1 - qrow0));
            float s2 = fmaf(sacc[nf][2], qscale, slope * (float)(key - qrow1));
            float s3 = fmaf(sacc[nf][3], qscale, slope * (float)(key + 1 - qrow1));
            if (maskt) {
                if (key > qrow0) s0 = -1e30f;
                if (key + 1 > qrow0) s1 = -1e30f;
                if (key > qrow1) s2 = -1e30f;
                if (key + 1 > qrow1) s3 = -1e30f;
            }
            sacc[nf][0] = s0; sacc[nf][1] = s1; sacc[nf][2] = s2; sacc[nf][3] = s3;
            mx0 = fmaxf(mx0, fmaxf(s0, s1));
            mx1 = fmaxf(mx1, fmaxf(s2, s3));
        }
        mx0 = fmaxf(mx0, __shfl_xor_sync(0xFFFFFFFFu, mx0, 1));
        mx0 = fmaxf(mx0, __shfl_xor_sync(0xFFFFFFFFu, mx0, 2));
        mx1 = fmaxf(mx1, __shfl_xor_sync(0xFFFFFFFFu, mx1, 1));
        mx1 = fmaxf(mx1, __shfl_xor_sync(0xFFFFFFFFu, mx1, 2));

        const float mn0 = fmaxf(m0, mx0);
        const float mn1 = fmaxf(m1, mx1);
        const float a0 = fexp2(m0 - mn0);
        const float a1 = fexp2(m1 - mn1);
        m0 = mn0; m1 = mn1;
        l0 *= a0; l1 *= a1;
#pragma unroll
        for (int nd = 0; nd < 8; ++nd) {
            oacc[nd][0] *= a0; oacc[nd][1] *= a0;
            oacc[nd][2] *= a1; oacc[nd][3] *= a1;
        }

        float rs0 = 0.f, rs1 = 0.f;
#pragma unroll
        for (int nf = 0; nf < 8; ++nf) {
            float p0 = fexp2(sacc[nf][0] - m0);
            float p1 = fexp2(sacc[nf][1] - m0);
            float p2 = fexp2(sacc[nf][2] - m1);
            float p3 = fexp2(sacc[nf][3] - m1);
            rs0 += p0 + p1; rs1 += p2 + p3;
            sacc[nf][0] = p0; sacc[nf][1] = p1; sacc[nf][2] = p2; sacc[nf][3] = p3;
        }
        rs0 += __shfl_xor_sync(0xFFFFFFFFu, rs0, 1);
        rs0 += __shfl_xor_sync(0xFFFFFFFFu, rs0, 2);
        rs1 += __shfl_xor_sync(0xFFFFFFFFu, rs1, 1);
        rs1 += __shfl_xor_sync(0xFFFFFFFFu, rs1, 2);
        l0 += rs0; l1 += rs1;

        uint32_t pah[4][4], pal[4][4];
#pragma unroll
        for (int jp = 0; jp < 4; ++jp) {
            const int j0 = 2 * jp, j1 = 2 * jp + 1;
            float e[8] = {sacc[j0][0], sacc[j0][1], sacc[j0][2], sacc[j0][3],
                          sacc[j1][0], sacc[j1][1], sacc[j1][2], sacc[j1][3]};
            float eh[8], el[8];
#pragma unroll
            for (int x = 0; x < 8; ++x) {
                __nv_bfloat16 hb = __float2bfloat16(e[x]);
                eh[x] = __bfloat162float(hb);
                el[x] = e[x] - eh[x];
            }
            pah[jp][0] = pack2bf(eh[0], eh[1]); pah[jp][1] = pack2bf(eh[2], eh[3]);
            pah[jp][2] = pack2bf(eh[4], eh[5]); pah[jp][3] = pack2bf(eh[6], eh[7]);
            pal[jp][0] = pack2bf(el[0], el[1]); pal[jp][1] = pack2bf(el[2], el[3]);
            pal[jp][2] = pack2bf(el[4], el[5]); pal[jp][3] = pack2bf(el[6], el[7]);
        }

#pragma unroll
        for (int jp = 0; jp < 4; ++jp) {
            uint32_t vbh[8][2], vbl[8][2];
#pragma unroll
            for (int p = 0; p < 4; ++p) {
                const int row = jp * 16 + rowoff;
                const int cch = 2 * p + khalf;
                const uint32_t off = row * 128 + ((cch ^ (row & 7)) << 4);
                uint32_t r[4];
                LDSM_X4_T(r, tb + 16384 + off);
                vbh[2 * p][0] = r[0]; vbh[2 * p][1] = r[1];
                vbh[2 * p + 1][0] = r[2]; vbh[2 * p + 1][1] = r[3];
                LDSM_X4_T(r, tb + 24576 + off);
                vbl[2 * p][0] = r[0]; vbl[2 * p][1] = r[1];
                vbl[2 * p + 1][0] = r[2]; vbl[2 * p + 1][1] = r[3];
            }
#pragma unroll
            for (int nd = 0; nd < 8; ++nd)
                MMA_BF16(oacc[nd], pah[jp], vbh[nd][0], vbh[nd][1]);
#pragma unroll
            for (int nd = 0; nd < 8; ++nd)
                MMA_BF16(oacc[nd], pal[jp], vbh[nd][0], vbh[nd][1]);
#pragma unroll
            for (int nd = 0; nd < 8; ++nd)
                MMA_BF16(oacc[nd], pah[jp], vbl[nd][0], vbl[nd][1]);
        }
        __syncthreads();
    }

    // epilogue: O /= l; write bf16 main + fp8 planes for proj GEMM
    const float il0 = 1.0f / l0;
    const float il1 = 1.0f / l1;
    const size_t r0off = (size_t)(b * TT + qrow0) * CC + h * 64;
    const size_t r1off = (size_t)(b * TT + qrow1) * CC + h * 64;
#pragma unroll
    for (int nd = 0; nd < 8; ++nd) {
        const int cd = nd * 8 + 2 * t;
        float y0 = oacc[nd][0] * il0, y1 = oacc[nd][1] * il0;
        float y2 = oacc[nd][2] * il1, y3 = oacc[nd][3] * il1;
        __nv_bfloat16 h0, h1; uint8_t a0, a1, r0, r1;
        tri_split(y0, h0, a0, r0); tri_split(y1, h1, a1, r1);
        *(__nv_bfloat162*)(g_ahi + r0off + cd) = __nv_bfloat162{h0, h1};
        *(uint16_t*)(g_a8 + r0off + cd)  = (uint16_t)a0 | ((uint16_t)a1 << 8);
        *(uint16_t*)(g_a8r + r0off + cd) = (uint16_t)r0 | ((uint16_t)r1 << 8);
        tri_split(y2, h0, a0, r0); tri_split(y3, h1, a1, r1);
        *(__nv_bfloat162*)(g_ahi + r1off + cd) = __nv_bfloat162{h0, h1};
        *(uint16_t*)(g_a8 + r1off + cd)  = (uint16_t)a0 | ((uint16_t)a1 << 8);
        *(uint16_t*)(g_a8r + r1off + cd) = (uint16_t)r0 | ((uint16_t)r1 << 8);
    }
}

// ---------------------------------------------------------------------------
// Harness entry
// ---------------------------------------------------------------------------
extern "C" void kernel_launch(void* const* d_in, const int* in_sizes, int n_in,
                              void* d_out, int out_size)
{
    const float* x      = (const float*)d_in[0];
    const float* W_attn = (const float*)d_in[1];
    const float* b_attn = (const float*)d_in[2];
    const float* W_proj = (const float*)d_in[3];
    const float* b_proj = (const float*)d_in[4];
    const float* temp   = (const float*)d_in[5];
    float* out = (float*)d_out;

    const int GEMM_SMEM = 3 * 49152;   // 147456
    const int ATTN_SMEM = 3 * 32768;   // 98304
    cudaFuncSetAttribute(hmma_gemm_kernel<3 * CC, 0>,
                         cudaFuncAttributeMaxDynamicSharedMemorySize, GEMM_SMEM);
    cudaFuncSetAttribute(hmma_gemm_kernel<CC, 1>,
                         cudaFuncAttributeMaxDynamicSharedMemorySize, GEMM_SMEM);
    cudaFuncSetAttribute(attn_mma_kernel,
                         cudaFuncAttributeMaxDynamicSharedMemorySize, ATTN_SMEM);

    // 0) tri-split inputs (bf16 main + fp8 + fp8 residual) + weight transposes
    split_x_kernel<<<(MM * CC / 4) / 256, 256>>>(x);
    tsplit_w_kernel<3 * CC, 0><<<dim3(3 * CC / 32, CC / 32), dim3(32, 8)>>>(W_attn);
    tsplit_w_kernel<CC, 1><<<dim3(CC / 32, CC / 32), dim3(32, 8)>>>(W_proj);

    // 1) QKV = x @ W_attn + b_attn  (bf16 main + fp8 cross HMMA)
    hmma_gemm_kernel<3 * CC, 0><<<dim3(3 * CC / 128, MM / 128), 256, GEMM_SMEM>>>(
        b_attn, nullptr);

    // 2) tensor-core causal ALiBi attention -> bf16+fp8 A for proj
    attn_mma_kernel<<<dim3(TT / 128, BB * HH), 256, ATTN_SMEM>>>(temp);

    // 3) out = att @ W_proj + b_proj  (bf16 main + fp8 cross HMMA)
    hmma_gemm_kernel<CC, 1><<<dim3(CC / 128, MM / 128), 256, GEMM_SMEM>>>(
        b_proj, out);
}

// round 12
// speedup vs baseline: 1.2504x; 1.2504x over previous
#include <cuda_runtime.h>
#include <cuda_bf16.h>
#include <cuda_fp16.h>
#include <cstdint>

// Problem constants
#define BB 2
#define TT 2048
#define CC 1024
#define HH 16
#define DD 64
#define MM (BB * TT)   // 4096 rows

// ---------------------------------------------------------------------------
// Device scratch (allocation-free per harness rules)
// ---------------------------------------------------------------------------
// q/k bf16 hi/lo; v fp16 single plane. Layout (b,h,t,d), 128B rows.
__device__ __nv_bfloat16 g_qhi[(size_t)BB * HH * TT * DD];
__device__ __nv_bfloat16 g_qlo[(size_t)BB * HH * TT * DD];
__device__ __nv_bfloat16 g_khi[(size_t)BB * HH * TT * DD];
__device__ __nv_bfloat16 g_klo[(size_t)BB * HH * TT * DD];
__device__ __half        g_v16[(size_t)BB * HH * TT * DD];
// bf16 hi/lo precision splits for GEMM operands
__device__ __nv_bfloat16 g_xhi[(size_t)MM * CC];
__device__ __nv_bfloat16 g_xlo[(size_t)MM * CC];
__device__ __nv_bfloat16 g_wahi[(size_t)3 * CC * CC];
__device__ __nv_bfloat16 g_walo[(size_t)3 * CC * CC];
__device__ __nv_bfloat16 g_wphi[(size_t)CC * CC];
__device__ __nv_bfloat16 g_wplo[(size_t)CC * CC];
__device__ __nv_bfloat16 g_ahi[(size_t)MM * CC];
__device__ __nv_bfloat16 g_alo[(size_t)MM * CC];

// ---------------------------------------------------------------------------
// PTX helpers (sm_80+ portable: cp.async / ldmatrix / mma.sync)
// ---------------------------------------------------------------------------
__device__ __forceinline__ uint32_t smem_to_u32(const void* smem_ptr) {
    uint32_t addr;
    asm("{ .reg .u64 tmp; cvta.to.shared.u64 tmp, %1; cvt.u32.u64 %0, tmp; }"
        : "=r"(addr) : "l"(smem_ptr));
    return addr;
}

__device__ __forceinline__ void cpasync16(uint32_t s, const void* g) {
    asm volatile("cp.async.cg.shared.global [%0], [%1], 16;" :: "r"(s), "l"(g) : "memory");
}

#define CP_COMMIT()  asm volatile("cp.async.commit_group;" ::: "memory")
#define CP_WAIT(n)   asm volatile("cp.async.wait_group %0;" :: "n"(n) : "memory")

#define LDSM_X4(r, addr) \
    asm volatile("ldmatrix.sync.aligned.m8n8.x4.shared.b16 {%0,%1,%2,%3}, [%4];" \
        : "=r"((r)[0]), "=r"((r)[1]), "=r"((r)[2]), "=r"((r)[3]) : "r"(addr))

#define LDSM_X4_T(r, addr) \
    asm volatile("ldmatrix.sync.aligned.m8n8.x4.trans.shared.b16 {%0,%1,%2,%3}, [%4];" \
        : "=r"((r)[0]), "=r"((r)[1]), "=r"((r)[2]), "=r"((r)[3]) : "r"(addr))

#define MMA_BF16(c, a, b0, b1) \
    asm volatile("mma.sync.aligned.m16n8k16.row.col.f32.bf16.bf16.f32 " \
        "{%0,%1,%2,%3}, {%4,%5,%6,%7}, {%8,%9}, {%0,%1,%2,%3};" \
        : "+f"((c)[0]), "+f"((c)[1]), "+f"((c)[2]), "+f"((c)[3]) \
        : "r"((a)[0]), "r"((a)[1]), "r"((a)[2]), "r"((a)[3]), "r"(b0), "r"(b1))

#define MMA_FP16(c, a, b0, b1) \
    asm volatile("mma.sync.aligned.m16n8k16.row.col.f32.f16.f16.f32 " \
        "{%0,%1,%2,%3}, {%4,%5,%6,%7}, {%8,%9}, {%0,%1,%2,%3};" \
        : "+f"((c)[0]), "+f"((c)[1]), "+f"((c)[2]), "+f"((c)[3]) \
        : "r"((a)[0]), "r"((a)[1]), "r"((a)[2]), "r"((a)[3]), "r"(b0), "r"(b1))

// fast exp2 on the FMA pipe (no MUFU)
__device__ __forceinline__ float fexp2(float x) {
    x = fmaxf(x, -126.0f);
    float t = x + 12582912.0f;
    float r = t - 12582912.0f;
    float f = x - r;
    int e = (__float_as_int(t) + (127 - 0x400000)) << 23;
    float p = 1.5353361883e-4f;
    p = fmaf(p, f, 1.3398874403e-3f);
    p = fmaf(p, f, 9.6184373577e-3f);
    p = fmaf(p, f, 5.5503324712e-2f);
    p = fmaf(p, f, 2.4022647914e-1f);
    p = fmaf(p, f, 6.9314720286e-1f);
    p = fmaf(p, f, 1.0f);
    return p * __int_as_float(e);
}

// ---------------------------------------------------------------------------
// Precision split helpers
// ---------------------------------------------------------------------------
__device__ __forceinline__ void bf16_split(float v, __nv_bfloat16& h, __nv_bfloat16& l) {
    h = __float2bfloat16(v);
    l = __float2bfloat16(v - __bfloat162float(h));
}

__device__ __forceinline__ uint32_t pack2h(float x, float y) {
    __half2 v = __floats2half2_rn(x, y);
    return *(uint32_t*)&v;
}

__global__ __launch_bounds__(256) void split_x_kernel(const float* __restrict__ x) {
    size_t i = (size_t)blockIdx.x * 256 + threadIdx.x;
    float4 v = ((const float4*)x)[i];
    __nv_bfloat16 h0, h1, h2, h3, l0, l1, l2, l3;
    bf16_split(v.x, h0, l0); bf16_split(v.y, h1, l1);
    bf16_split(v.z, h2, l2); bf16_split(v.w, h3, l3);
    __nv_bfloat162* ph = (__nv_bfloat162*)(g_xhi + i * 4);
    __nv_bfloat162* pl = (__nv_bfloat162*)(g_xlo + i * 4);
    ph[0] = __nv_bfloat162{h0, h1}; ph[1] = __nv_bfloat162{h2, h3};
    pl[0] = __nv_bfloat162{l0, l1}; pl[1] = __nv_bfloat162{l2, l3};
}

template <int NN, int WHICH>
__global__ __launch_bounds__(256) void tsplit_w_kernel(const float* __restrict__ W) {
    __shared__ float tile[32][33];
    __nv_bfloat16* Whi = (WHICH == 0) ? g_wahi : g_wphi;
    __nv_bfloat16* Wlo = (WHICH == 0) ? g_walo : g_wplo;
    const int nb = blockIdx.x * 32;
    const int kb = blockIdx.y * 32;
    const int tx = threadIdx.x, ty = threadIdx.y;
#pragma unroll
    for (int r = 0; r < 4; ++r)
        tile[ty + r * 8][tx] = W[(size_t)(kb + ty + r * 8) * NN + nb + tx];
    __syncthreads();
#pragma unroll
    for (int r = 0; r < 4; ++r) {
        const int n = nb + ty + r * 8;
        const int k = kb + tx;
        float v = tile[tx][ty + r * 8];
        __nv_bfloat16 h, l;
        bf16_split(v, h, l);
        Whi[(size_t)n * 1024 + k] = h;
        Wlo[(size_t)n * 1024 + k] = l;
    }
}

// ---------------------------------------------------------------------------
// bf16x3 tensor-core GEMM (exact R8 schedule — proven 243us QKV):
// CTA tile 128x128, K-chunk 32 bf16 (64B rows, xor swizzle), 3-stage
// cp.async pipeline, one __syncthreads per iteration, 2 CTAs/SM.
// MODE 0: scatter q/k as bf16 hi/lo, v as fp16.  MODE 1: att -> Out.
// SMEM stage 32KB: Ahi@0 Alo@8192 Bhi@16384 Blo@24576.
// ---------------------------------------------------------------------------
template <int Ndim, int MODE>
__global__ __launch_bounds__(256, 2) void hmma_gemm_kernel(
    const float* __restrict__ bias, float* __restrict__ Out)
{
    extern __shared__ __align__(1024) char smem[];
    const uint32_t sbase = smem_to_u32(smem);
    const int tid = threadIdx.x;
    const int lane = tid & 31;
    const int wid = tid >> 5;
    const int wm = wid >> 2;
    const int wn = wid & 3;
    const int m0 = blockIdx.y * 128;
    const int n0 = blockIdx.x * 128;
    constexpr int KT = 32;

    const __nv_bfloat16* Ahi = (MODE == 0) ? g_xhi : g_ahi;
    const __nv_bfloat16* Alo = (MODE == 0) ? g_xlo : g_alo;
    const __nv_bfloat16* Bhi = (MODE == 0) ? g_wahi : g_wphi;
    const __nv_bfloat16* Blo = (MODE == 0) ? g_walo : g_wplo;

    const char* gAh = (const char*)Ahi + (size_t)m0 * 2048;
    const char* gAl = (const char*)Alo + (size_t)m0 * 2048;
    const char* gBh = (const char*)Bhi + (size_t)n0 * 2048;
    const char* gBl = (const char*)Blo + (size_t)n0 * 2048;

    float acc[4][4][4];
#pragma unroll
    for (int mf = 0; mf < 4; ++mf)
#pragma unroll
        for (int nf = 0; nf < 4; ++nf)
#pragma unroll
            for (int e = 0; e < 4; ++e) acc[mf][nf][e] = 0.f;

    auto issue = [&](int c) {
        const uint32_t tb = sbase + (uint32_t)(c % 3) * 32768;
        const int kb = c * 64;
#pragma unroll
        for (int i = 0; i < 2; ++i) {
            const int idx = tid + i * 256;
            const int row = idx >> 2;
            const int ch = idx & 3;
            const uint32_t soff = row * 64 + ((ch ^ ((row >> 1) & 3)) << 4);
            const size_t goff = (size_t)row * 2048 + ch * 16 + kb;
            cpasync16(tb + 0     + soff, gAh + goff);
            cpasync16(tb + 8192  + soff, gAl + goff);
            cpasync16(tb + 16384 + soff, gBh + goff);
            cpasync16(tb + 24576 + soff, gBl + goff);
        }
        CP_COMMIT();
    };

    issue(0);
    issue(1);

    const int q8 = lane >> 3;
    const int iq = lane & 7;
    const int rowoff_a = ((q8 & 1) << 3) + iq;
    const int khalf = q8 >> 1;

    for (int c = 0; c < KT; ++c) {
        CP_WAIT(1);
        __syncthreads();
        if (c + 2 < KT) issue(c + 2);

        const uint32_t tb = sbase + (uint32_t)(c % 3) * 32768;
        const uint32_t aT = tb, alT = tb + 8192, bT = tb + 16384, blT = tb + 24576;

#pragma unroll
        for (int ks = 0; ks < 2; ++ks) {
            const int cch = ks * 2 + khalf;
            uint32_t ah[4][4], al[4][4];
#pragma unroll
            for (int mf = 0; mf < 4; ++mf) {
                const int row = wm * 64 + mf * 16 + rowoff_a;
                const uint32_t off = row * 64 + ((cch ^ ((row >> 1) & 3)) << 4);
                LDSM_X4(ah[mf], aT + off);
                LDSM_X4(al[mf], alT + off);
            }
            uint32_t bh[4][2], bl[4][2];
#pragma unroll
            for (int np = 0; np < 2; ++np) {
                const int row = wn * 32 + np * 16 + rowoff_a;
                const uint32_t off = row * 64 + ((cch ^ ((row >> 1) & 3)) << 4);
                uint32_t r[4];
                LDSM_X4(r, bT + off);
                bh[2 * np][0] = r[0]; bh[2 * np][1] = r[2];
                bh[2 * np + 1][0] = r[1]; bh[2 * np + 1][1] = r[3];
                LDSM_X4(r, blT + off);
                bl[2 * np][0] = r[0]; bl[2 * np][1] = r[2];
                bl[2 * np + 1][0] = r[1]; bl[2 * np + 1][1] = r[3];
            }
#pragma unroll
            for (int mf = 0; mf < 4; ++mf)
#pragma unroll
                for (int nf = 0; nf < 4; ++nf)
                    MMA_BF16(acc[mf][nf], ah[mf], bh[nf][0], bh[nf][1]);
#pragma unroll
            for (int mf = 0; mf < 4; ++mf)
#pragma unroll
                for (int nf = 0; nf < 4; ++nf)
                    MMA_BF16(acc[mf][nf], ah[mf], bl[nf][0], bl[nf][1]);
#pragma unroll
            for (int mf = 0; mf < 4; ++mf)
#pragma unroll
                for (int nf = 0; nf < 4; ++nf)
                    MMA_BF16(acc[mf][nf], al[mf], bh[nf][0], bh[nf][1]);
        }
    }

    const int g = lane >> 2, t = lane & 3;
#pragma unroll
    for (int mf = 0; mf < 4; ++mf) {
        const int r_lo = m0 + wm * 64 + mf * 16 + g;
#pragma unroll
        for (int nf = 0; nf < 4; ++nf) {
            const int col = n0 + wn * 32 + nf * 8 + 2 * t;
            const float b0 = bias[col], b1 = bias[col + 1];
            float v00 = acc[mf][nf][0] + b0, v01 = acc[mf][nf][1] + b1;
            float v10 = acc[mf][nf][2] + b0, v11 = acc[mf][nf][3] + b1;
            if (MODE == 0) {
                const int which = col >> 10;
                const int ci = col & 1023;
                const int hh = ci >> 6;
                const int dd = ci & 63;
                const int b_lo = r_lo >> 11, t_lo = r_lo & 2047;
                const int r_hi = r_lo + 8;
                const int b_hi = r_hi >> 11, t_hi = r_hi & 2047;
                size_t off0 = (((size_t)b_lo * HH + hh) * TT + t_lo) * DD + dd;
                size_t off1 = (((size_t)b_hi * HH + hh) * TT + t_hi) * DD + dd;
                if (which == 2) {
                    // V: fp16 single plane
                    *(uint32_t*)(g_v16 + off0) = pack2h(v00, v01);
                    *(uint32_t*)(g_v16 + off1) = pack2h(v10, v11);
                } else {
                    __nv_bfloat16* dh = (which == 0) ? g_qhi : g_khi;
                    __nv_bfloat16* dl = (which == 0) ? g_qlo : g_klo;
                    __nv_bfloat16 h0, h1, l0, l1;
                    bf16_split(v00, h0, l0); bf16_split(v01, h1, l1);
                    *(__nv_bfloat162*)(dh + off0) = __nv_bfloat162{h0, h1};
                    *(__nv_bfloat162*)(dl + off0) = __nv_bfloat162{l0, l1};
                    bf16_split(v10, h0, l0); bf16_split(v11, h1, l1);
                    *(__nv_bfloat162*)(dh + off1) = __nv_bfloat162{h0, h1};
                    *(__nv_bfloat162*)(dl + off1) = __nv_bfloat162{l0, l1};
                }
            } else {
                *(float2*)(Out + (size_t)r_lo * Ndim + col) = float2{v00, v01};
                *(float2*)(Out + (size_t)(r_lo + 8) * Ndim + col) = float2{v10, v11};
            }
        }
    }
}

// ---------------------------------------------------------------------------
// Tensor-core flash attention with ALiBi + temperature.
// QK^T: bf16x3 (unchanged). P*V: fp16 single-pass (P fp16, V fp16) —
// 128 warp-MMAs per k-tile instead of 192, and lighter packing.
// SMEM: Q stage 32KB @0 (hi 16K, lo 16K); KV buffers @32768 + buf*24576:
//       Khi@0 Klo@8192 V16@16384 (8KB each: 64 rows x 128B).
// ---------------------------------------------------------------------------
__global__ __launch_bounds__(256) void attn_mma_kernel(const float* __restrict__ temp)
{
    extern __shared__ __align__(1024) char smem[];
    const uint32_t sb = smem_to_u32(smem);
    const int tid = threadIdx.x;
    const int lane = tid & 31;
    const int wid = tid >> 5;
    const int bh = blockIdx.y;
    const int qt = (int)gridDim.x - 1 - blockIdx.x;   // heavy tiles first
    const int b = bh >> 4;
    const int h = bh & 15;

    const float qscale = 0.125f * (1.0f / temp[0]) * 1.44269504088896340736f;
    const float slope = exp2f(-0.5f * (float)(h + 1)) * 1.44269504088896340736f;

    const int q8 = lane >> 3;
    const int iq = lane & 7;
    const int rowoff = ((q8 & 1) << 3) + iq;
    const int khalf = q8 >> 1;
    const int g = lane >> 2, t = lane & 3;

    const char* gQh = (const char*)g_qhi + ((size_t)bh * TT + qt * 128) * 128;
    const char* gQl = (const char*)g_qlo + ((size_t)bh * TT + qt * 128) * 128;
    const char* gKh = (const char*)g_khi + (size_t)bh * TT * 128;
    const char* gKl = (const char*)g_klo + (size_t)bh * TT * 128;
    const char* gV  = (const char*)g_v16 + (size_t)bh * TT * 128;

    const int nkt = 2 * qt + 2;

    // stage Q (group 0)
#pragma unroll
    for (int i = 0; i < 4; ++i) {
        const int idx = tid + i * 256;
        const int row = idx >> 3;
        const int ch = idx & 7;
        const uint32_t soff = row * 128 + ((ch ^ (row & 7)) << 4);
        const size_t goff = (size_t)row * 128 + ch * 16;
        cpasync16(sb + 0     + soff, gQh + goff);
        cpasync16(sb + 16384 + soff, gQl + goff);
    }
    CP_COMMIT();

    auto issue_kv = [&](int kt) {
        const uint32_t tb = sb + 32768 + (uint32_t)(kt & 1) * 24576;
        const size_t kbase = (size_t)kt * 64 * 128;
#pragma unroll
        for (int i = 0; i < 2; ++i) {
            const int idx = tid + i * 256;
            const int row = idx >> 3;
            const int ch = idx & 7;
            const uint32_t soff = row * 128 + ((ch ^ (row & 7)) << 4);
            const size_t goff = kbase + (size_t)row * 128 + ch * 16;
            cpasync16(tb + 0     + soff, gKh + goff);
            cpasync16(tb + 8192  + soff, gKl + goff);
            cpasync16(tb + 16384 + soff, gV  + goff);
        }
        CP_COMMIT();
    };

    issue_kv(0);
    CP_WAIT(1);
    __syncthreads();

    uint32_t qh[4][4], ql[4][4];
#pragma unroll
    for (int ks = 0; ks < 4; ++ks) {
        const int row = wid * 16 + rowoff;
        const int cch = ks * 2 + khalf;
        const uint32_t off = row * 128 + ((cch ^ (row & 7)) << 4);
        LDSM_X4(qh[ks], sb + off);
        LDSM_X4(ql[ks], sb + 16384 + off);
    }

    float oacc[8][4];
#pragma unroll
    for (int nd = 0; nd < 8; ++nd)
#pragma unroll
        for (int e = 0; e < 4; ++e) oacc[nd][e] = 0.f;
    float m0 = -1e30f, m1 = -1e30f, l0 = 0.f, l1 = 0.f;

    const int qrow0 = qt * 128 + wid * 16 + g;
    const int qrow1 = qrow0 + 8;

    for (int kt = 0; kt < nkt; ++kt) {
        if (kt + 1 < nkt) { issue_kv(kt + 1); CP_WAIT(1); }
        else              { CP_WAIT(0); }
        __syncthreads();

        const uint32_t tb = sb + 32768 + (uint32_t)(kt & 1) * 24576;

        // ---- S = Q K^T (bf16x3) ----
        float sacc[8][4];
#pragma unroll
        for (int nf = 0; nf < 8; ++nf)
#pragma unroll
            for (int e = 0; e < 4; ++e) sacc[nf][e] = 0.f;

#pragma unroll
        for (int ks = 0; ks < 4; ++ks) {
            const int cch = ks * 2 + khalf;
            uint32_t kbh[8][2], kbl[8][2];
#pragma unroll
            for (int np = 0; np < 4; ++np) {
                const int row = np * 16 + rowoff;
                const uint32_t off = row * 128 + ((cch ^ (row & 7)) << 4);
                uint32_t r[4];
                LDSM_X4(r, tb + off);
                kbh[2 * np][0] = r[0]; kbh[2 * np][1] = r[2];
                kbh[2 * np + 1][0] = r[1]; kbh[2 * np + 1][1] = r[3];
                LDSM_X4(r, tb + 8192 + off);
                kbl[2 * np][0] = r[0]; kbl[2 * np][1] = r[2];
                kbl[2 * np + 1][0] = r[1]; kbl[2 * np + 1][1] = r[3];
            }
#pragma unroll
            for (int nf = 0; nf < 8; ++nf)
                MMA_BF16(sacc[nf], qh[ks], kbh[nf][0], kbh[nf][1]);
#pragma unroll
            for (int nf = 0; nf < 8; ++nf)
                MMA_BF16(sacc[nf], qh[ks], kbl[nf][0], kbl[nf][1]);
#pragma unroll
            for (int nf = 0; nf < 8; ++nf)
                MMA_BF16(sacc[nf], ql[ks], kbh[nf][0], kbh[nf][1]);
        }

        // ---- softmax (online) ----
        const bool maskt = (kt >= 2 * qt);
        float mx0 = -1e30f, mx1 = -1e30f;
#pragma unroll
        for (int nf = 0; nf < 8; ++nf) {
            const int key = kt * 64 + nf * 8 + 2 * t;
            float s0 = fmaf(sacc[nf][0], qscale, slope * (float)(key - qrow0));
            float s1 = fmaf(sacc[nf][1], qscale, slope * (float)(key + 1 - qrow0));
            float s2 = fmaf(sacc[nf][2], qscale, slope * (float)(key - qrow1));
            float s3 = fmaf(sacc[nf][3], qscale, slope * (float)(key + 1 - qrow1));
            if (maskt) {
                if (key > qrow0) s0 = -1e30f;
                if (key + 1 > qrow0) s1 = -1e30f;
                if (key > qrow1) s2 = -1e30f;
                if (key + 1 > qrow1) s3 = -1e30f;
            }
            sacc[nf][0] = s0; sacc[nf][1] = s1; sacc[nf][2] = s2; sacc[nf][3] = s3;
            mx0 = fmaxf(mx0, fmaxf(s0, s1));
            mx1 = fmaxf(mx1, fmaxf(s2, s3));
        }
        mx0 = fmaxf(mx0, __shfl_xor_sync(0xFFFFFFFFu, mx0, 1));
        mx0 = fmaxf(mx0, __shfl_xor_sync(0xFFFFFFFFu, mx0, 2));
        mx1 = fmaxf(mx1, __shfl_xor_sync(0xFFFFFFFFu, mx1, 1));
        mx1 = fmaxf(mx1, __shfl_xor_sync(0xFFFFFFFFu, mx1, 2));

        const float mn0 = fmaxf(m0, mx0);
        const float mn1 = fmaxf(m1, mx1);
        const float a0 = fexp2(m0 - mn0);
        const float a1 = fexp2(m1 - mn1);
        m0 = mn0; m1 = mn1;
        l0 *= a0; l1 *= a1;
#pragma unroll
        for (int nd = 0; nd < 8; ++nd) {
            oacc[nd][0] *= a0; oacc[nd][1] *= a0;
            oacc[nd][2] *= a1; oacc[nd][3] *= a1;
        }

        float rs0 = 0.f, rs1 = 0.f;
#pragma unroll
        for (int nf = 0; nf < 8; ++nf) {
            float p0 = fexp2(sacc[nf][0] - m0);
            float p1 = fexp2(sacc[nf][1] - m0);
            float p2 = fexp2(sacc[nf][2] - m1);
            float p3 = fexp2(sacc[nf][3] - m1);
            rs0 += p0 + p1; rs1 += p2 + p3;
            sacc[nf][0] = p0; sacc[nf][1] = p1; sacc[nf][2] = p2; sacc[nf][3] = p3;
        }
        rs0 += __shfl_xor_sync(0xFFFFFFFFu, rs0, 1);
        rs0 += __shfl_xor_sync(0xFFFFFFFFu, rs0, 2);
        rs1 += __shfl_xor_sync(0xFFFFFFFFu, rs1, 1);
        rs1 += __shfl_xor_sync(0xFFFFFFFFu, rs1, 2);
        l0 += rs0; l1 += rs1;

        // ---- pack P to fp16 A-frags (single pass) ----
        uint32_t pa[4][4];
#pragma unroll
        for (int jp = 0; jp < 4; ++jp) {
            const int j0 = 2 * jp, j1 = 2 * jp + 1;
            pa[jp][0] = pack2h(sacc[j0][0], sacc[j0][1]);
            pa[jp][1] = pack2h(sacc[j0][2], sacc[j0][3]);
            pa[jp][2] = pack2h(sacc[j1][0], sacc[j1][1]);
            pa[jp][3] = pack2h(sacc[j1][2], sacc[j1][3]);
        }

        // ---- O += P V (fp16 single) ----
#pragma unroll
        for (int jp = 0; jp < 4; ++jp) {
            uint32_t vb[8][2];
#pragma unroll
            for (int p = 0; p < 4; ++p) {
                const int row = jp * 16 + rowoff;
                const int cch = 2 * p + khalf;
                const uint32_t off = row * 128 + ((cch ^ (row & 7)) << 4);
                uint32_t r[4];
                LDSM_X4_T(r, tb + 16384 + off);
                vb[2 * p][0] = r[0]; vb[2 * p][1] = r[1];
                vb[2 * p + 1][0] = r[2]; vb[2 * p + 1][1] = r[3];
            }
#pragma unroll
            for (int nd = 0; nd < 8; ++nd)
                MMA_FP16(oacc[nd], pa[jp], vb[nd][0], vb[nd][1]);
        }
        __syncthreads();
    }

    // epilogue: O /= l; write bf16 hi/lo A operand for proj GEMM
    const float il0 = 1.0f / l0;
    const float il1 = 1.0f / l1;
    const size_t r0off = (size_t)(b * TT + qrow0) * CC + h * 64;
    const size_t r1off = (size_t)(b * TT + qrow1) * CC + h * 64;
#pragma unroll
    for (int nd = 0; nd < 8; ++nd) {
        const int cd = nd * 8 + 2 * t;
        float y0 = oacc[nd][0] * il0, y1 = oacc[nd][1] * il0;
        float y2 = oacc[nd][2] * il1, y3 = oacc[nd][3] * il1;
        __nv_bfloat16 h0, h1, l0b, l1b;
        bf16_split(y0, h0, l0b); bf16_split(y1, h1, l1b);
        *(__nv_bfloat162*)(g_ahi + r0off + cd) = __nv_bfloat162{h0, h1};
        *(__nv_bfloat162*)(g_alo + r0off + cd) = __nv_bfloat162{l0b, l1b};
        bf16_split(y2, h0, l0b); bf16_split(y3, h1, l1b);
        *(__nv_bfloat162*)(g_ahi + r1off + cd) = __nv_bfloat162{h0, h1};
        *(__nv_bfloat162*)(g_alo + r1off + cd) = __nv_bfloat162{l0b, l1b};
    }
}

// ---------------------------------------------------------------------------
// Harness entry
// ---------------------------------------------------------------------------
extern "C" void kernel_launch(void* const* d_in, const int* in_sizes, int n_in,
                              void* d_out, int out_size)
{
    const float* x      = (const float*)d_in[0];
    const float* W_attn = (const float*)d_in[1];
    const float* b_attn = (const float*)d_in[2];
    const float* W_proj = (const float*)d_in[3];
    const float* b_proj = (const float*)d_in[4];
    const float* temp   = (const float*)d_in[5];
    float* out = (float*)d_out;

    const int GEMM_SMEM = 3 * 32768;             // 98304
    const int ATTN_SMEM = 32768 + 2 * 24576;     // 81920
    cudaFuncSetAttribute(hmma_gemm_kernel<3 * CC, 0>,
                         cudaFuncAttributeMaxDynamicSharedMemorySize, GEMM_SMEM);
    cudaFuncSetAttribute(hmma_gemm_kernel<CC, 1>,
                         cudaFuncAttributeMaxDynamicSharedMemorySize, GEMM_SMEM);
    cudaFuncSetAttribute(attn_mma_kernel,
                         cudaFuncAttributeMaxDynamicSharedMemorySize, ATTN_SMEM);

    // 0) precision-split inputs (bf16 hi/lo) + weight transposes
    split_x_kernel<<<(MM * CC / 4) / 256, 256>>>(x);
    tsplit_w_kernel<3 * CC, 0><<<dim3(3 * CC / 32, CC / 32), dim3(32, 8)>>>(W_attn);
    tsplit_w_kernel<CC, 1><<<dim3(CC / 32, CC / 32), dim3(32, 8)>>>(W_proj);

    // 1) QKV = x @ W_attn + b_attn  (bf16x3 HMMA; q/k bf16 hi/lo, v fp16)
    hmma_gemm_kernel<3 * CC, 0><<<dim3(3 * CC / 128, MM / 128), 256, GEMM_SMEM>>>(
        b_attn, nullptr);

    // 2) tensor-core causal ALiBi attention (fp16 PV) -> bf16-split A
    attn_mma_kernel<<<dim3(TT / 128, BB * HH), 256, ATTN_SMEM>>>(temp);

    // 3) out = att @ W_proj + b_proj  (bf16x3 HMMA)
    hmma_gemm_kernel<CC, 1><<<dim3(CC / 128, MM / 128), 256, GEMM_SMEM>>>(
        b_proj, out);
}

// round 13
// speedup vs baseline: 2.4155x; 1.9317x over previous
#include <cuda_runtime.h>
#include <cuda_bf16.h>
#include <cuda_fp16.h>
#include <cstdint>

// Problem constants
#define BB 2
#define TT 2048
#define CC 1024
#define HH 16
#define DD 64
#define MM (BB * TT)   // 4096 rows

// ---------------------------------------------------------------------------
// Device scratch (allocation-free per harness rules) — all fp16 single-plane
// ---------------------------------------------------------------------------
__device__ __half g_q16[(size_t)BB * HH * TT * DD];   // (b,h,t,d), 128B rows
__device__ __half g_k16[(size_t)BB * HH * TT * DD];
__device__ __half g_v16[(size_t)BB * HH * TT * DD];
__device__ __half g_x16 [(size_t)MM * CC];            // x   [M][K]
__device__ __half g_wa16[(size_t)3 * CC * CC];        // W_attn^T [N][K]
__device__ __half g_wp16[(size_t)CC * CC];            // W_proj^T [N][K]
__device__ __half g_a16 [(size_t)MM * CC];            // attention out [M][K]

// ---------------------------------------------------------------------------
// PTX helpers (sm_80+ portable: cp.async / ldmatrix / mma.sync)
// ---------------------------------------------------------------------------
__device__ __forceinline__ uint32_t smem_to_u32(const void* smem_ptr) {
    uint32_t addr;
    asm("{ .reg .u64 tmp; cvta.to.shared.u64 tmp, %1; cvt.u32.u64 %0, tmp; }"
        : "=r"(addr) : "l"(smem_ptr));
    return addr;
}

__device__ __forceinline__ void cpasync16(uint32_t s, const void* g) {
    asm volatile("cp.async.cg.shared.global [%0], [%1], 16;" :: "r"(s), "l"(g) : "memory");
}

#define CP_COMMIT()  asm volatile("cp.async.commit_group;" ::: "memory")
#define CP_WAIT(n)   asm volatile("cp.async.wait_group %0;" :: "n"(n) : "memory")

#define LDSM_X4(r, addr) \
    asm volatile("ldmatrix.sync.aligned.m8n8.x4.shared.b16 {%0,%1,%2,%3}, [%4];" \
        : "=r"((r)[0]), "=r"((r)[1]), "=r"((r)[2]), "=r"((r)[3]) : "r"(addr))

#define LDSM_X4_T(r, addr) \
    asm volatile("ldmatrix.sync.aligned.m8n8.x4.trans.shared.b16 {%0,%1,%2,%3}, [%4];" \
        : "=r"((r)[0]), "=r"((r)[1]), "=r"((r)[2]), "=r"((r)[3]) : "r"(addr))

#define MMA_FP16(c, a, b0, b1) \
    asm volatile("mma.sync.aligned.m16n8k16.row.col.f32.f16.f16.f32 " \
        "{%0,%1,%2,%3}, {%4,%5,%6,%7}, {%8,%9}, {%0,%1,%2,%3};" \
        : "+f"((c)[0]), "+f"((c)[1]), "+f"((c)[2]), "+f"((c)[3]) \
        : "r"((a)[0]), "r"((a)[1]), "r"((a)[2]), "r"((a)[3]), "r"(b0), "r"(b1))

// fast exp2 on the FMA pipe (no MUFU)
__device__ __forceinline__ float fexp2(float x) {
    x = fmaxf(x, -126.0f);
    float t = x + 12582912.0f;
    float r = t - 12582912.0f;
    float f = x - r;
    int e = (__float_as_int(t) + (127 - 0x400000)) << 23;
    float p = 1.5353361883e-4f;
    p = fmaf(p, f, 1.3398874403e-3f);
    p = fmaf(p, f, 9.6184373577e-3f);
    p = fmaf(p, f, 5.5503324712e-2f);
    p = fmaf(p, f, 2.4022647914e-1f);
    p = fmaf(p, f, 6.9314720286e-1f);
    p = fmaf(p, f, 1.0f);
    return p * __int_as_float(e);
}

__device__ __forceinline__ uint32_t pack2h(float x, float y) {
    __half2 v = __floats2half2_rn(x, y);
    return *(uint32_t*)&v;
}

// ---------------------------------------------------------------------------
// Preprocessing
// ---------------------------------------------------------------------------
__global__ __launch_bounds__(256) void split_x_kernel(const float* __restrict__ x) {
    size_t i = (size_t)blockIdx.x * 256 + threadIdx.x;   // MM*CC/4 float4s
    float4 v = ((const float4*)x)[i];
    uint2 o;
    o.x = pack2h(v.x, v.y);
    o.y = pack2h(v.z, v.w);
    *(uint2*)(g_x16 + i * 4) = o;
}

// Transpose: W [K=1024][NN] fp32 -> Wt fp16 [NN][1024]
template <int NN, int WHICH>
__global__ __launch_bounds__(256) void tsplit_w_kernel(const float* __restrict__ W) {
    __shared__ float tile[32][33];
    __half* Wd = (WHICH == 0) ? g_wa16 : g_wp16;
    const int nb = blockIdx.x * 32;
    const int kb = blockIdx.y * 32;
    const int tx = threadIdx.x, ty = threadIdx.y;
#pragma unroll
    for (int r = 0; r < 4; ++r)
        tile[ty + r * 8][tx] = W[(size_t)(kb + ty + r * 8) * NN + nb + tx];
    __syncthreads();
#pragma unroll
    for (int r = 0; r < 4; ++r) {
        const int n = nb + ty + r * 8;
        const int k = kb + tx;
        Wd[(size_t)n * 1024 + k] = __float2half(tile[tx][ty + r * 8]);
    }
}

// ---------------------------------------------------------------------------
// fp16 tensor-core GEMM (R8 schedule, single plane): C = A @ Wt^T + bias
// CTA tile 128x128, K-chunk 32 fp16 (64B rows, xor swizzle ch^((row>>1)&3)),
// 3-stage cp.async pipeline, one __syncthreads per iteration, 2 CTAs/SM.
// 1 MMA per (mf,nf) per k16.  SMEM stage 16KB: A@0 (8KB), B@8192 (8KB).
// MODE 0: scatter q/k/v fp16.  MODE 1: att -> Out fp32.
// ---------------------------------------------------------------------------
template <int Ndim, int MODE>
__global__ __launch_bounds__(256, 2) void hmma_gemm_kernel(
    const float* __restrict__ bias, float* __restrict__ Out)
{
    extern __shared__ __align__(1024) char smem[];
    const uint32_t sbase = smem_to_u32(smem);
    const int tid = threadIdx.x;
    const int lane = tid & 31;
    const int wid = tid >> 5;
    const int wm = wid >> 2;
    const int wn = wid & 3;
    const int m0 = blockIdx.y * 128;
    const int n0 = blockIdx.x * 128;
    constexpr int KT = 32;

    const __half* Aop = (MODE == 0) ? g_x16 : g_a16;
    const __half* Bop = (MODE == 0) ? g_wa16 : g_wp16;

    const char* gA = (const char*)Aop + (size_t)m0 * 2048;  // row = 1024 fp16 = 2048B
    const char* gB = (const char*)Bop + (size_t)n0 * 2048;

    float acc[4][4][4];
#pragma unroll
    for (int mf = 0; mf < 4; ++mf)
#pragma unroll
        for (int nf = 0; nf < 4; ++nf)
#pragma unroll
            for (int e = 0; e < 4; ++e) acc[mf][nf][e] = 0.f;

    auto issue = [&](int c) {
        const uint32_t tb = sbase + (uint32_t)(c % 3) * 16384;
        const int kb = c * 64;
#pragma unroll
        for (int i = 0; i < 2; ++i) {
            const int idx = tid + i * 256;
            const int row = idx >> 2;
            const int ch = idx & 3;
            const uint32_t soff = row * 64 + ((ch ^ ((row >> 1) & 3)) << 4);
            const size_t goff = (size_t)row * 2048 + ch * 16 + kb;
            cpasync16(tb + 0    + soff, gA + goff);
            cpasync16(tb + 8192 + soff, gB + goff);
        }
        CP_COMMIT();
    };

    issue(0);
    issue(1);

    const int q8 = lane >> 3;
    const int iq = lane & 7;
    const int rowoff_a = ((q8 & 1) << 3) + iq;
    const int khalf = q8 >> 1;

    for (int c = 0; c < KT; ++c) {
        CP_WAIT(1);
        __syncthreads();
        if (c + 2 < KT) issue(c + 2);

        const uint32_t tb = sbase + (uint32_t)(c % 3) * 16384;

#pragma unroll
        for (int ks = 0; ks < 2; ++ks) {
            const int cch = ks * 2 + khalf;
            uint32_t af[4][4];
#pragma unroll
            for (int mf = 0; mf < 4; ++mf) {
                const int row = wm * 64 + mf * 16 + rowoff_a;
                const uint32_t off = row * 64 + ((cch ^ ((row >> 1) & 3)) << 4);
                LDSM_X4(af[mf], tb + off);
            }
#pragma unroll
            for (int np = 0; np < 2; ++np) {
                const int row = wn * 32 + np * 16 + rowoff_a;
                const uint32_t off = row * 64 + ((cch ^ ((row >> 1) & 3)) << 4);
                uint32_t r[4];
                LDSM_X4(r, tb + 8192 + off);
                const int nf0 = 2 * np, nf1 = 2 * np + 1;
#pragma unroll
                for (int mf = 0; mf < 4; ++mf) {
                    MMA_FP16(acc[mf][nf0], af[mf], r[0], r[2]);
                    MMA_FP16(acc[mf][nf1], af[mf], r[1], r[3]);
                }
            }
        }
    }

    // Epilogue. Frag map: c0,c1 -> (row g, cols 2t,2t+1); c2,c3 -> row g+8.
    const int g = lane >> 2, t = lane & 3;
#pragma unroll
    for (int mf = 0; mf < 4; ++mf) {
        const int r_lo = m0 + wm * 64 + mf * 16 + g;
#pragma unroll
        for (int nf = 0; nf < 4; ++nf) {
            const int col = n0 + wn * 32 + nf * 8 + 2 * t;
            const float b0 = bias[col], b1 = bias[col + 1];
            float v00 = acc[mf][nf][0] + b0, v01 = acc[mf][nf][1] + b1;
            float v10 = acc[mf][nf][2] + b0, v11 = acc[mf][nf][3] + b1;
            if (MODE == 0) {
                const int which = col >> 10;
                const int ci = col & 1023;
                const int hh = ci >> 6;
                const int dd = ci & 63;
                __half* dst = (which == 0) ? g_q16 : ((which == 1) ? g_k16 : g_v16);
                const int b_lo = r_lo >> 11, t_lo = r_lo & 2047;
                const int r_hi = r_lo + 8;
                const int b_hi = r_hi >> 11, t_hi = r_hi & 2047;
                size_t off0 = (((size_t)b_lo * HH + hh) * TT + t_lo) * DD + dd;
                size_t off1 = (((size_t)b_hi * HH + hh) * TT + t_hi) * DD + dd;
                *(uint32_t*)(dst + off0) = pack2h(v00, v01);
                *(uint32_t*)(dst + off1) = pack2h(v10, v11);
            } else {
                *(float2*)(Out + (size_t)r_lo * Ndim + col) = float2{v00, v01};
                *(float2*)(Out + (size_t)(r_lo + 8) * Ndim + col) = float2{v10, v11};
            }
        }
    }
}

// ---------------------------------------------------------------------------
// Tensor-core flash attention with ALiBi + temperature, all-fp16 MMAs.
// QK^T: fp16 single (logits tiny in log2 domain -> quantization negligible).
// P*V: fp16 single (validated R11). 64 warp-MMAs per k-tile (was 128).
// SMEM: Q stage 16KB @0; KV buffers @16384 + buf*16384: K@0 V@8192.
// ---------------------------------------------------------------------------
__global__ __launch_bounds__(256) void attn_mma_kernel(const float* __restrict__ temp)
{
    extern __shared__ __align__(1024) char smem[];
    const uint32_t sb = smem_to_u32(smem);
    const int tid = threadIdx.x;
    const int lane = tid & 31;
    const int wid = tid >> 5;
    const int bh = blockIdx.y;
    const int qt = (int)gridDim.x - 1 - blockIdx.x;   // heavy tiles first
    const int b = bh >> 4;
    const int h = bh & 15;

    const float qscale = 0.125f * (1.0f / temp[0]) * 1.44269504088896340736f;
    const float slope = exp2f(-0.5f * (float)(h + 1)) * 1.44269504088896340736f;

    const int q8 = lane >> 3;
    const int iq = lane & 7;
    const int rowoff = ((q8 & 1) << 3) + iq;
    const int khalf = q8 >> 1;
    const int g = lane >> 2, t = lane & 3;

    const char* gQ = (const char*)g_q16 + ((size_t)bh * TT + qt * 128) * 128;
    const char* gK = (const char*)g_k16 + (size_t)bh * TT * 128;
    const char* gV = (const char*)g_v16 + (size_t)bh * TT * 128;

    const int nkt = 2 * qt + 2;

    // stage Q (16KB: 128 rows x 128B)
#pragma unroll
    for (int i = 0; i < 4; ++i) {
        const int idx = tid + i * 256;
        const int row = idx >> 3;
        const int ch = idx & 7;
        const uint32_t soff = row * 128 + ((ch ^ (row & 7)) << 4);
        cpasync16(sb + soff, gQ + (size_t)row * 128 + ch * 16);
    }
    CP_COMMIT();

    auto issue_kv = [&](int kt) {
        const uint32_t tb = sb + 16384 + (uint32_t)(kt & 1) * 16384;
        const size_t kbase = (size_t)kt * 64 * 128;
#pragma unroll
        for (int i = 0; i < 2; ++i) {
            const int idx = tid + i * 256;
            const int row = idx >> 3;
            const int ch = idx & 7;
            const uint32_t soff = row * 128 + ((ch ^ (row & 7)) << 4);
            const size_t goff = kbase + (size_t)row * 128 + ch * 16;
            cpasync16(tb + 0    + soff, gK + goff);
            cpasync16(tb + 8192 + soff, gV + goff);
        }
        CP_COMMIT();
    };

    issue_kv(0);
    CP_WAIT(1);
    __syncthreads();

    // Q fragments resident (4 k16-steps)
    uint32_t qf[4][4];
#pragma unroll
    for (int ks = 0; ks < 4; ++ks) {
        const int row = wid * 16 + rowoff;
        const int cch = ks * 2 + khalf;
        const uint32_t off = row * 128 + ((cch ^ (row & 7)) << 4);
        LDSM_X4(qf[ks], sb + off);
    }

    float oacc[8][4];
#pragma unroll
    for (int nd = 0; nd < 8; ++nd)
#pragma unroll
        for (int e = 0; e < 4; ++e) oacc[nd][e] = 0.f;
    float m0 = -1e30f, m1 = -1e30f, l0 = 0.f, l1 = 0.f;

    const int qrow0 = qt * 128 + wid * 16 + g;
    const int qrow1 = qrow0 + 8;

    for (int kt = 0; kt < nkt; ++kt) {
        if (kt + 1 < nkt) { issue_kv(kt + 1); CP_WAIT(1); }
        else              { CP_WAIT(0); }
        __syncthreads();

        const uint32_t tb = sb + 16384 + (uint32_t)(kt & 1) * 16384;

        // ---- S = Q K^T (fp16) ----
        float sacc[8][4];
#pragma unroll
        for (int nf = 0; nf < 8; ++nf)
#pragma unroll
            for (int e = 0; e < 4; ++e) sacc[nf][e] = 0.f;

#pragma unroll
        for (int ks = 0; ks < 4; ++ks) {
            const int cch = ks * 2 + khalf;
#pragma unroll
            for (int np = 0; np < 4; ++np) {
                const int row = np * 16 + rowoff;
                const uint32_t off = row * 128 + ((cch ^ (row & 7)) << 4);
                uint32_t r[4];
                LDSM_X4(r, tb + off);
                MMA_FP16(sacc[2 * np],     qf[ks], r[0], r[2]);
                MMA_FP16(sacc[2 * np + 1], qf[ks], r[1], r[3]);
            }
        }

        // ---- softmax (online) ----
        const bool maskt = (kt >= 2 * qt);
        float mx0 = -1e30f, mx1 = -1e30f;
#pragma unroll
        for (int nf = 0; nf < 8; ++nf) {
            const int key = kt * 64 + nf * 8 + 2 * t;
            float s0 = fmaf(sacc[nf][0], qscale, slope * (float)(key - qrow0));
            float s1 = fmaf(sacc[nf][1], qscale, slope * (float)(key + 1 - qrow0));
            float s2 = fmaf(sacc[nf][2], qscale, slope * (float)(key - qrow1));
            float s3 = fmaf(sacc[nf][3], qscale, slope * (float)(key + 1 - qrow1));
            if (maskt) {
                if (key > qrow0) s0 = -1e30f;
                if (key + 1 > qrow0) s1 = -1e30f;
                if (key > qrow1) s2 = -1e30f;
                if (key + 1 > qrow1) s3 = -1e30f;
            }
            sacc[nf][0] = s0; sacc[nf][1] = s1; sacc[nf][2] = s2; sacc[nf][3] = s3;
            mx0 = fmaxf(mx0, fmaxf(s0, s1));
            mx1 = fmaxf(mx1, fmaxf(s2, s3));
        }
        mx0 = fmaxf(mx0, __shfl_xor_sync(0xFFFFFFFFu, mx0, 1));
        mx0 = fmaxf(mx0, __shfl_xor_sync(0xFFFFFFFFu, mx0, 2));
        mx1 = fmaxf(mx1, __shfl_xor_sync(0xFFFFFFFFu, mx1, 1));
        mx1 = fmaxf(mx1, __shfl_xor_sync(0xFFFFFFFFu, mx1, 2));

        const float mn0 = fmaxf(m0, mx0);
        const float mn1 = fmaxf(m1, mx1);
        const float a0 = fexp2(m0 - mn0);
        const float a1 = fexp2(m1 - mn1);
        m0 = mn0; m1 = mn1;
        l0 *= a0; l1 *= a1;
#pragma unroll
        for (int nd = 0; nd < 8; ++nd) {
            oacc[nd][0] *= a0; oacc[nd][1] *= a0;
            oacc[nd][2] *= a1; oacc[nd][3] *= a1;
        }

        float rs0 = 0.f, rs1 = 0.f;
#pragma unroll
        for (int nf = 0; nf < 8; ++nf) {
            float p0 = fexp2(sacc[nf][0] - m0);
            float p1 = fexp2(sacc[nf][1] - m0);
            float p2 = fexp2(sacc[nf][2] - m1);
            float p3 = fexp2(sacc[nf][3] - m1);
            rs0 += p0 + p1; rs1 += p2 + p3;
            sacc[nf][0] = p0; sacc[nf][1] = p1; sacc[nf][2] = p2; sacc[nf][3] = p3;
        }
        rs0 += __shfl_xor_sync(0xFFFFFFFFu, rs0, 1);
        rs0 += __shfl_xor_sync(0xFFFFFFFFu, rs0, 2);
        rs1 += __shfl_xor_sync(0xFFFFFFFFu, rs1, 1);
        rs1 += __shfl_xor_sync(0xFFFFFFFFu, rs1, 2);
        l0 += rs0; l1 += rs1;

        // ---- pack P to fp16 A-frags ----
        uint32_t pa[4][4];
#pragma unroll
        for (int jp = 0; jp < 4; ++jp) {
            const int j0 = 2 * jp, j1 = 2 * jp + 1;
            pa[jp][0] = pack2h(sacc[j0][0], sacc[j0][1]);
            pa[jp][1] = pack2h(sacc[j0][2], sacc[j0][3]);
            pa[jp][2] = pack2h(sacc[j1][0], sacc[j1][1]);
            pa[jp][3] = pack2h(sacc[j1][2], sacc[j1][3]);
        }

        // ---- O += P V (fp16) ----
#pragma unroll
        for (int jp = 0; jp < 4; ++jp) {
            uint32_t vb[8][2];
#pragma unroll
            for (int p = 0; p < 4; ++p) {
                const int row = jp * 16 + rowoff;
                const int cch = 2 * p + khalf;
                const uint32_t off = row * 128 + ((cch ^ (row & 7)) << 4);
                uint32_t r[4];
                LDSM_X4_T(r, tb + 8192 + off);
                vb[2 * p][0] = r[0]; vb[2 * p][1] = r[1];
                vb[2 * p + 1][0] = r[2]; vb[2 * p + 1][1] = r[3];
            }
#pragma unroll
            for (int nd = 0; nd < 8; ++nd)
                MMA_FP16(oacc[nd], pa[jp], vb[nd][0], vb[nd][1]);
        }
        __syncthreads();
    }

    // epilogue: O /= l; write fp16 A operand for proj GEMM
    const float il0 = 1.0f / l0;
    const float il1 = 1.0f / l1;
    const size_t r0off = (size_t)(b * TT + qrow0) * CC + h * 64;
    const size_t r1off = (size_t)(b * TT + qrow1) * CC + h * 64;
#pragma unroll
    for (int nd = 0; nd < 8; ++nd) {
        const int cd = nd * 8 + 2 * t;
        *(uint32_t*)(g_a16 + r0off + cd) = pack2h(oacc[nd][0] * il0, oacc[nd][1] * il0);
        *(uint32_t*)(g_a16 + r1off + cd) = pack2h(oacc[nd][2] * il1, oacc[nd][3] * il1);
    }
}

// ---------------------------------------------------------------------------
// Harness entry
// ---------------------------------------------------------------------------
extern "C" void kernel_launch(void* const* d_in, const int* in_sizes, int n_in,
                              void* d_out, int out_size)
{
    const float* x      = (const float*)d_in[0];
    const float* W_attn = (const float*)d_in[1];
    const float* b_attn = (const float*)d_in[2];
    const float* W_proj = (const float*)d_in[3];
    const float* b_proj = (const float*)d_in[4];
    const float* temp   = (const float*)d_in[5];
    float* out = (float*)d_out;

    const int GEMM_SMEM = 3 * 16384;             // 49152
    const int ATTN_SMEM = 16384 + 2 * 16384;     // 49152
    cudaFuncSetAttribute(hmma_gemm_kernel<3 * CC, 0>,
                         cudaFuncAttributeMaxDynamicSharedMemorySize, GEMM_SMEM);
    cudaFuncSetAttribute(hmma_gemm_kernel<CC, 1>,
                         cudaFuncAttributeMaxDynamicSharedMemorySize, GEMM_SMEM);
    cudaFuncSetAttribute(attn_mma_kernel,
                         cudaFuncAttributeMaxDynamicSharedMemorySize, ATTN_SMEM);

    // 0) fp16 conversions (x) + weight transposes
    split_x_kernel<<<(MM * CC / 4) / 256, 256>>>(x);
    tsplit_w_kernel<3 * CC, 0><<<dim3(3 * CC / 32, CC / 32), dim3(32, 8)>>>(W_attn);
    tsplit_w_kernel<CC, 1><<<dim3(CC / 32, CC / 32), dim3(32, 8)>>>(W_proj);

    // 1) QKV = x @ W_attn + b_attn  (fp16 HMMA; q/k/v fp16)
    hmma_gemm_kernel<3 * CC, 0><<<dim3(3 * CC / 128, MM / 128), 256, GEMM_SMEM>>>(
        b_attn, nullptr);

    // 2) tensor-core causal ALiBi attention (all fp16 MMAs) -> fp16 A
    attn_mma_kernel<<<dim3(TT / 128, BB * HH), 256, ATTN_SMEM>>>(temp);

    // 3) out = att @ W_proj + b_proj  (fp16 HMMA)
    hmma_gemm_kernel<CC, 1><<<dim3(CC / 128, MM / 128), 256, GEMM_SMEM>>>(
        b_proj, out);
}

// round 14
// speedup vs baseline: 2.6108x; 1.0809x over previous
#include <cuda_runtime.h>
#include <cuda_bf16.h>
#include <cuda_fp16.h>
#include <cstdint>

// Problem constants
#define BB 2
#define TT 2048
#define CC 1024
#define HH 16
#define DD 64
#define MM (BB * TT)   // 4096 rows

// ---------------------------------------------------------------------------
// Device scratch (allocation-free per harness rules) — all fp16 single-plane
// ---------------------------------------------------------------------------
__device__ __half g_q16[(size_t)BB * HH * TT * DD];   // (b,h,t,d), 128B rows
__device__ __half g_k16[(size_t)BB * HH * TT * DD];
__device__ __half g_v16[(size_t)BB * HH * TT * DD];
__device__ __half g_x16 [(size_t)MM * CC];            // x   [M][K]
__device__ __half g_wa16[(size_t)3 * CC * CC];        // W_attn^T [N][K]
__device__ __half g_wp16[(size_t)CC * CC];            // W_proj^T [N][K]
__device__ __half g_a16 [(size_t)MM * CC];            // attention out [M][K]

// ---------------------------------------------------------------------------
// PTX helpers (sm_80+ portable: cp.async / ldmatrix / mma.sync)
// ---------------------------------------------------------------------------
__device__ __forceinline__ uint32_t smem_to_u32(const void* smem_ptr) {
    uint32_t addr;
    asm("{ .reg .u64 tmp; cvta.to.shared.u64 tmp, %1; cvt.u32.u64 %0, tmp; }"
        : "=r"(addr) : "l"(smem_ptr));
    return addr;
}

__device__ __forceinline__ void cpasync16(uint32_t s, const void* g) {
    asm volatile("cp.async.cg.shared.global [%0], [%1], 16;" :: "r"(s), "l"(g) : "memory");
}

#define CP_COMMIT()  asm volatile("cp.async.commit_group;" ::: "memory")
#define CP_WAIT(n)   asm volatile("cp.async.wait_group %0;" :: "n"(n) : "memory")

#define LDSM_X4(r, addr) \
    asm volatile("ldmatrix.sync.aligned.m8n8.x4.shared.b16 {%0,%1,%2,%3}, [%4];" \
        : "=r"((r)[0]), "=r"((r)[1]), "=r"((r)[2]), "=r"((r)[3]) : "r"(addr))

#define LDSM_X4_T(r, addr) \
    asm volatile("ldmatrix.sync.aligned.m8n8.x4.trans.shared.b16 {%0,%1,%2,%3}, [%4];" \
        : "=r"((r)[0]), "=r"((r)[1]), "=r"((r)[2]), "=r"((r)[3]) : "r"(addr))

#define MMA_FP16(c, a, b0, b1) \
    asm volatile("mma.sync.aligned.m16n8k16.row.col.f32.f16.f16.f32 " \
        "{%0,%1,%2,%3}, {%4,%5,%6,%7}, {%8,%9}, {%0,%1,%2,%3};" \
        : "+f"((c)[0]), "+f"((c)[1]), "+f"((c)[2]), "+f"((c)[3]) \
        : "r"((a)[0]), "r"((a)[1]), "r"((a)[2]), "r"((a)[3]), "r"(b0), "r"(b1))

// fast exp2 on the FMA pipe (no MUFU)
__device__ __forceinline__ float fexp2(float x) {
    x = fmaxf(x, -126.0f);
    float t = x + 12582912.0f;
    float r = t - 12582912.0f;
    float f = x - r;
    int e = (__float_as_int(t) + (127 - 0x400000)) << 23;
    float p = 1.5353361883e-4f;
    p = fmaf(p, f, 1.3398874403e-3f);
    p = fmaf(p, f, 9.6184373577e-3f);
    p = fmaf(p, f, 5.5503324712e-2f);
    p = fmaf(p, f, 2.4022647914e-1f);
    p = fmaf(p, f, 6.9314720286e-1f);
    p = fmaf(p, f, 1.0f);
    return p * __int_as_float(e);
}

__device__ __forceinline__ uint32_t pack2h(float x, float y) {
    __half2 v = __floats2half2_rn(x, y);
    return *(uint32_t*)&v;
}

// ---------------------------------------------------------------------------
// Preprocessing
// ---------------------------------------------------------------------------
__global__ __launch_bounds__(256) void split_x_kernel(const float* __restrict__ x) {
    size_t i = (size_t)blockIdx.x * 256 + threadIdx.x;   // MM*CC/4 float4s
    float4 v = ((const float4*)x)[i];
    uint2 o;
    o.x = pack2h(v.x, v.y);
    o.y = pack2h(v.z, v.w);
    *(uint2*)(g_x16 + i * 4) = o;
}

// Transpose: W [K=1024][NN] fp32 -> Wt fp16 [NN][1024]
template <int NN, int WHICH>
__global__ __launch_bounds__(256) void tsplit_w_kernel(const float* __restrict__ W) {
    __shared__ float tile[32][33];
    __half* Wd = (WHICH == 0) ? g_wa16 : g_wp16;
    const int nb = blockIdx.x * 32;
    const int kb = blockIdx.y * 32;
    const int tx = threadIdx.x, ty = threadIdx.y;
#pragma unroll
    for (int r = 0; r < 4; ++r)
        tile[ty + r * 8][tx] = W[(size_t)(kb + ty + r * 8) * NN + nb + tx];
    __syncthreads();
#pragma unroll
    for (int r = 0; r < 4; ++r) {
        const int n = nb + ty + r * 8;
        const int k = kb + tx;
        Wd[(size_t)n * 1024 + k] = __float2half(tile[tx][ty + r * 8]);
    }
}

// ---------------------------------------------------------------------------
// fp16 tensor-core GEMM: C = A[M,K] @ Wt[N,K]^T + bias
// CTA tile 256x128 (raised intensity: A-tile x2 n-warps + B-tile x4 m-warps
// = 64KB crossbar per chunk for 1M MACs, 1.5x better than 128x128).
// 8 warps as 4(m) x 2(n); warp tile 64x64 = 4 m-frags x 8 n-frags.
// K-chunk 32 fp16 (64B rows, xor swizzle), 3-stage cp.async pipeline.
// SMEM stage 24KB: A@0 (16KB, 256 rows), B@16384 (8KB, 128 rows).
// MODE 0: scatter q/k/v fp16.  MODE 1: att -> Out fp32.
// ---------------------------------------------------------------------------
template <int Ndim, int MODE>
__global__ __launch_bounds__(256, 1) void hmma_gemm_kernel(
    const float* __restrict__ bias, float* __restrict__ Out)
{
    extern __shared__ __align__(1024) char smem[];
    const uint32_t sbase = smem_to_u32(smem);
    const int tid = threadIdx.x;
    const int lane = tid & 31;
    const int wid = tid >> 5;
    const int wm = wid >> 1;   // 0..3
    const int wn = wid & 1;    // 0..1
    const int m0 = blockIdx.y * 256;
    const int n0 = blockIdx.x * 128;
    constexpr int KT = 32;
    constexpr int STG = 24576;

    const __half* Aop = (MODE == 0) ? g_x16 : g_a16;
    const __half* Bop = (MODE == 0) ? g_wa16 : g_wp16;

    const char* gA = (const char*)Aop + (size_t)m0 * 2048;  // row = 1024 fp16 = 2048B
    const char* gB = (const char*)Bop + (size_t)n0 * 2048;

    float acc[4][8][4];
#pragma unroll
    for (int mf = 0; mf < 4; ++mf)
#pragma unroll
        for (int nf = 0; nf < 8; ++nf)
#pragma unroll
            for (int e = 0; e < 4; ++e) acc[mf][nf][e] = 0.f;

    auto issue = [&](int c) {
        const uint32_t tb = sbase + (uint32_t)(c % 3) * STG;
        const int kb = c * 64;
        // A: 256 rows x 4 chunks = 1024 (4/thread)
#pragma unroll
        for (int i = 0; i < 4; ++i) {
            const int idx = tid + i * 256;
            const int row = idx >> 2;
            const int ch = idx & 3;
            const uint32_t soff = row * 64 + ((ch ^ ((row >> 1) & 3)) << 4);
            cpasync16(tb + soff, gA + (size_t)row * 2048 + ch * 16 + kb);
        }
        // B: 128 rows x 4 chunks = 512 (2/thread)
#pragma unroll
        for (int i = 0; i < 2; ++i) {
            const int idx = tid + i * 256;
            const int row = idx >> 2;
            const int ch = idx & 3;
            const uint32_t soff = row * 64 + ((ch ^ ((row >> 1) & 3)) << 4);
            cpasync16(tb + 16384 + soff, gB + (size_t)row * 2048 + ch * 16 + kb);
        }
        CP_COMMIT();
    };

    issue(0);
    issue(1);

    const int q8 = lane >> 3;
    const int iq = lane & 7;
    const int rowoff_a = ((q8 & 1) << 3) + iq;
    const int khalf = q8 >> 1;

    for (int c = 0; c < KT; ++c) {
        CP_WAIT(1);
        __syncthreads();
        if (c + 2 < KT) issue(c + 2);

        const uint32_t tb = sbase + (uint32_t)(c % 3) * STG;

#pragma unroll
        for (int ks = 0; ks < 2; ++ks) {
            const int cch = ks * 2 + khalf;
            uint32_t af[4][4];
#pragma unroll
            for (int mf = 0; mf < 4; ++mf) {
                const int row = wm * 64 + mf * 16 + rowoff_a;
                const uint32_t off = row * 64 + ((cch ^ ((row >> 1) & 3)) << 4);
                LDSM_X4(af[mf], tb + off);
            }
#pragma unroll
            for (int np = 0; np < 4; ++np) {
                const int row = wn * 64 + np * 16 + rowoff_a;
                const uint32_t off = row * 64 + ((cch ^ ((row >> 1) & 3)) << 4);
                uint32_t r[4];
                LDSM_X4(r, tb + 16384 + off);
                const int nf0 = 2 * np, nf1 = 2 * np + 1;
#pragma unroll
                for (int mf = 0; mf < 4; ++mf) {
                    MMA_FP16(acc[mf][nf0], af[mf], r[0], r[2]);
                    MMA_FP16(acc[mf][nf1], af[mf], r[1], r[3]);
                }
            }
        }
    }

    // Epilogue. Frag map: c0,c1 -> (row g, cols 2t,2t+1); c2,c3 -> row g+8.
    const int g = lane >> 2, t = lane & 3;
#pragma unroll
    for (int mf = 0; mf < 4; ++mf) {
        const int r_lo = m0 + wm * 64 + mf * 16 + g;
#pragma unroll
        for (int nf = 0; nf < 8; ++nf) {
            const int col = n0 + wn * 64 + nf * 8 + 2 * t;
            const float b0 = bias[col], b1 = bias[col + 1];
            float v00 = acc[mf][nf][0] + b0, v01 = acc[mf][nf][1] + b1;
            float v10 = acc[mf][nf][2] + b0, v11 = acc[mf][nf][3] + b1;
            if (MODE == 0) {
                const int which = col >> 10;
                const int ci = col & 1023;
                const int hh = ci >> 6;
                const int dd = ci & 63;
                __half* dst = (which == 0) ? g_q16 : ((which == 1) ? g_k16 : g_v16);
                const int b_lo = r_lo >> 11, t_lo = r_lo & 2047;
                const int r_hi = r_lo + 8;
                const int b_hi = r_hi >> 11, t_hi = r_hi & 2047;
                size_t off0 = (((size_t)b_lo * HH + hh) * TT + t_lo) * DD + dd;
                size_t off1 = (((size_t)b_hi * HH + hh) * TT + t_hi) * DD + dd;
                *(uint32_t*)(dst + off0) = pack2h(v00, v01);
                *(uint32_t*)(dst + off1) = pack2h(v10, v11);
            } else {
                *(float2*)(Out + (size_t)r_lo * Ndim + col) = float2{v00, v01};
                *(float2*)(Out + (size_t)(r_lo + 8) * Ndim + col) = float2{v10, v11};
            }
        }
    }
}

// ---------------------------------------------------------------------------
// Tensor-core flash attention, all-fp16 MMAs, 128-thread CTAs (64 q-rows).
// Smaller CTAs -> ~3 CTAs/SM (reg-limited) for latency hiding + finer
// causal load balance (1024 CTAs, heavy tiles first).
// SMEM: Q @0 (8KB: 64 rows x 128B); KV buffers @8192 + buf*16384: K@0 V@8192.
// ---------------------------------------------------------------------------
__global__ __launch_bounds__(128, 3) void attn_mma_kernel(const float* __restrict__ temp)
{
    extern __shared__ __align__(1024) char smem[];
    const uint32_t sb = smem_to_u32(smem);
    const int tid = threadIdx.x;
    const int lane = tid & 31;
    const int wid = tid >> 5;          // 0..3
    const int bh = blockIdx.y;
    const int qt = (int)gridDim.x - 1 - blockIdx.x;   // heavy tiles first
    const int b = bh >> 4;
    const int h = bh & 15;

    const float qscale = 0.125f * (1.0f / temp[0]) * 1.44269504088896340736f;
    const float slope = exp2f(-0.5f * (float)(h + 1)) * 1.44269504088896340736f;

    const int q8 = lane >> 3;
    const int iq = lane & 7;
    const int rowoff = ((q8 & 1) << 3) + iq;
    const int khalf = q8 >> 1;
    const int g = lane >> 2, t = lane & 3;

    const char* gQ = (const char*)g_q16 + ((size_t)bh * TT + qt * 64) * 128;
    const char* gK = (const char*)g_k16 + (size_t)bh * TT * 128;
    const char* gV = (const char*)g_v16 + (size_t)bh * TT * 128;

    const int nkt = qt + 1;   // 64-key tiles (causal)

    // stage Q (8KB: 64 rows x 128B; 512 chunks / 128 threads = 4 each)
#pragma unroll
    for (int i = 0; i < 4; ++i) {
        const int idx = tid + i * 128;
        const int row = idx >> 3;
        const int ch = idx & 7;
        const uint32_t soff = row * 128 + ((ch ^ (row & 7)) << 4);
        cpasync16(sb + soff, gQ + (size_t)row * 128 + ch * 16);
    }
    CP_COMMIT();

    auto issue_kv = [&](int kt) {
        const uint32_t tb = sb + 8192 + (uint32_t)(kt & 1) * 16384;
        const size_t kbase = (size_t)kt * 64 * 128;
#pragma unroll
        for (int i = 0; i < 4; ++i) {
            const int idx = tid + i * 128;
            const int row = idx >> 3;
            const int ch = idx & 7;
            const uint32_t soff = row * 128 + ((ch ^ (row & 7)) << 4);
            const size_t goff = kbase + (size_t)row * 128 + ch * 16;
            cpasync16(tb + 0    + soff, gK + goff);
            cpasync16(tb + 8192 + soff, gV + goff);
        }
        CP_COMMIT();
    };

    issue_kv(0);
    CP_WAIT(1);
    __syncthreads();

    // Q fragments resident (4 k16-steps; warp owns rows wid*16..wid*16+15)
    uint32_t qf[4][4];
#pragma unroll
    for (int ks = 0; ks < 4; ++ks) {
        const int row = wid * 16 + rowoff;
        const int cch = ks * 2 + khalf;
        const uint32_t off = row * 128 + ((cch ^ (row & 7)) << 4);
        LDSM_X4(qf[ks], sb + off);
    }

    float oacc[8][4];
#pragma unroll
    for (int nd = 0; nd < 8; ++nd)
#pragma unroll
        for (int e = 0; e < 4; ++e) oacc[nd][e] = 0.f;
    float m0 = -1e30f, m1 = -1e30f, l0 = 0.f, l1 = 0.f;

    const int qrow0 = qt * 64 + wid * 16 + g;
    const int qrow1 = qrow0 + 8;

    for (int kt = 0; kt < nkt; ++kt) {
        if (kt + 1 < nkt) { issue_kv(kt + 1); CP_WAIT(1); }
        else              { CP_WAIT(0); }
        __syncthreads();

        const uint32_t tb = sb + 8192 + (uint32_t)(kt & 1) * 16384;

        // ---- S = Q K^T (fp16) ----
        float sacc[8][4];
#pragma unroll
        for (int nf = 0; nf < 8; ++nf)
#pragma unroll
            for (int e = 0; e < 4; ++e) sacc[nf][e] = 0.f;

#pragma unroll
        for (int ks = 0; ks < 4; ++ks) {
            const int cch = ks * 2 + khalf;
#pragma unroll
            for (int np = 0; np < 4; ++np) {
                const int row = np * 16 + rowoff;
                const uint32_t off = row * 128 + ((cch ^ (row & 7)) << 4);
                uint32_t r[4];
                LDSM_X4(r, tb + off);
                MMA_FP16(sacc[2 * np],     qf[ks], r[0], r[2]);
                MMA_FP16(sacc[2 * np + 1], qf[ks], r[1], r[3]);
            }
        }

        // ---- softmax (online) ----
        const bool maskt = (kt == qt);
        float mx0 = -1e30f, mx1 = -1e30f;
#pragma unroll
        for (int nf = 0; nf < 8; ++nf) {
            const int key = kt * 64 + nf * 8 + 2 * t;
            float s0 = fmaf(sacc[nf][0], qscale, slope * (float)(key - qrow0));
            float s1 = fmaf(sacc[nf][1], qscale, slope * (float)(key + 1 - qrow0));
            float s2 = fmaf(sacc[nf][2], qscale, slope * (float)(key - qrow1));
            float s3 = fmaf(sacc[nf][3], qscale, slope * (float)(key + 1 - qrow1));
            if (maskt) {
                if (key > qrow0) s0 = -1e30f;
                if (key + 1 > qrow0) s1 = -1e30f;
                if (key > qrow1) s2 = -1e30f;
                if (key + 1 > qrow1) s3 = -1e30f;
            }
            sacc[nf][0] = s0; sacc[nf][1] = s1; sacc[nf][2] = s2; sacc[nf][3] = s3;
            mx0 = fmaxf(mx0, fmaxf(s0, s1));
            mx1 = fmaxf(mx1, fmaxf(s2, s3));
        }
        mx0 = fmaxf(mx0, __shfl_xor_sync(0xFFFFFFFFu, mx0, 1));
        mx0 = fmaxf(mx0, __shfl_xor_sync(0xFFFFFFFFu, mx0, 2));
        mx1 = fmaxf(mx1, __shfl_xor_sync(0xFFFFFFFFu, mx1, 1));
        mx1 = fmaxf(mx1, __shfl_xor_sync(0xFFFFFFFFu, mx1, 2));

        const float mn0 = fmaxf(m0, mx0);
        const float mn1 = fmaxf(m1, mx1);
        const float a0 = fexp2(m0 - mn0);
        const float a1 = fexp2(m1 - mn1);
        m0 = mn0; m1 = mn1;
        l0 *= a0; l1 *= a1;
#pragma unroll
        for (int nd = 0; nd < 8; ++nd) {
            oacc[nd][0] *= a0; oacc[nd][1] *= a0;
            oacc[nd][2] *= a1; oacc[nd][3] *= a1;
        }

        float rs0 = 0.f, rs1 = 0.f;
#pragma unroll
        for (int nf = 0; nf < 8; ++nf) {
            float p0 = fexp2(sacc[nf][0] - m0);
            float p1 = fexp2(sacc[nf][1] - m0);
            float p2 = fexp2(sacc[nf][2] - m1);
            float p3 = fexp2(sacc[nf][3] - m1);
            rs0 += p0 + p1; rs1 += p2 + p3;
            sacc[nf][0] = p0; sacc[nf][1] = p1; sacc[nf][2] = p2; sacc[nf][3] = p3;
        }
        rs0 += __shfl_xor_sync(0xFFFFFFFFu, rs0, 1);
        rs0 += __shfl_xor_sync(0xFFFFFFFFu, rs0, 2);
        rs1 += __shfl_xor_sync(0xFFFFFFFFu, rs1, 1);
        rs1 += __shfl_xor_sync(0xFFFFFFFFu, rs1, 2);
        l0 += rs0; l1 += rs1;

        // ---- pack P to fp16 A-frags ----
        uint32_t pa[4][4];
#pragma unroll
        for (int jp = 0; jp < 4; ++jp) {
            const int j0 = 2 * jp, j1 = 2 * jp + 1;
            pa[jp][0] = pack2h(sacc[j0][0], sacc[j0][1]);
            pa[jp][1] = pack2h(sacc[j0][2], sacc[j0][3]);
            pa[jp][2] = pack2h(sacc[j1][0], sacc[j1][1]);
            pa[jp][3] = pack2h(sacc[j1][2], sacc[j1][3]);
        }

        // ---- O += P V (fp16) ----
#pragma unroll
        for (int jp = 0; jp < 4; ++jp) {
            uint32_t vb[8][2];
#pragma unroll
            for (int p = 0; p < 4; ++p) {
                const int row = jp * 16 + rowoff;
                const int cch = 2 * p + khalf;
                const uint32_t off = row * 128 + ((cch ^ (row & 7)) << 4);
                uint32_t r[4];
                LDSM_X4_T(r, tb + 8192 + off);
                vb[2 * p][0] = r[0]; vb[2 * p][1] = r[1];
                vb[2 * p + 1][0] = r[2]; vb[2 * p + 1][1] = r[3];
            }
#pragma unroll
            for (int nd = 0; nd < 8; ++nd)
                MMA_FP16(oacc[nd], pa[jp], vb[nd][0], vb[nd][1]);
        }
        __syncthreads();
    }

    // epilogue: O /= l; write fp16 A operand for proj GEMM
    const float il0 = 1.0f / l0;
    const float il1 = 1.0f / l1;
    const size_t r0off = (size_t)(b * TT + qrow0) * CC + h * 64;
    const size_t r1off = (size_t)(b * TT + qrow1) * CC + h * 64;
#pragma unroll
    for (int nd = 0; nd < 8; ++nd) {
        const int cd = nd * 8 + 2 * t;
        *(uint32_t*)(g_a16 + r0off + cd) = pack2h(oacc[nd][0] * il0, oacc[nd][1] * il0);
        *(uint32_t*)(g_a16 + r1off + cd) = pack2h(oacc[nd][2] * il1, oacc[nd][3] * il1);
    }
}

// ---------------------------------------------------------------------------
// Harness entry
// ---------------------------------------------------------------------------
extern "C" void kernel_launch(void* const* d_in, const int* in_sizes, int n_in,
                              void* d_out, int out_size)
{
    const float* x      = (const float*)d_in[0];
    const float* W_attn = (const float*)d_in[1];
    const float* b_attn = (const float*)d_in[2];
    const float* W_proj = (const float*)d_in[3];
    const float* b_proj = (const float*)d_in[4];
    const float* temp   = (const float*)d_in[5];
    float* out = (float*)d_out;

    const int GEMM_SMEM = 3 * 24576;            // 73728
    const int ATTN_SMEM = 8192 + 2 * 16384;     // 40960
    cudaFuncSetAttribute(hmma_gemm_kernel<3 * CC, 0>,
                         cudaFuncAttributeMaxDynamicSharedMemorySize, GEMM_SMEM);
    cudaFuncSetAttribute(hmma_gemm_kernel<CC, 1>,
                         cudaFuncAttributeMaxDynamicSharedMemorySize, GEMM_SMEM);
    cudaFuncSetAttribute(attn_mma_kernel,
                         cudaFuncAttributeMaxDynamicSharedMemorySize, ATTN_SMEM);

    // 0) fp16 conversions (x) + weight transposes
    split_x_kernel<<<(MM * CC / 4) / 256, 256>>>(x);
    tsplit_w_kernel<3 * CC, 0><<<dim3(3 * CC / 32, CC / 32), dim3(32, 8)>>>(W_attn);
    tsplit_w_kernel<CC, 1><<<dim3(CC / 32, CC / 32), dim3(32, 8)>>>(W_proj);

    // 1) QKV = x @ W_attn + b_attn  (fp16 HMMA, 256x128 tiles)
    hmma_gemm_kernel<3 * CC, 0><<<dim3(3 * CC / 128, MM / 256), 256, GEMM_SMEM>>>(
        b_attn, nullptr);

    // 2) tensor-core causal ALiBi attention (128-thread CTAs) -> fp16 A
    attn_mma_kernel<<<dim3(TT / 64, BB * HH), 128, ATTN_SMEM>>>(temp);

    // 3) out = att @ W_proj + b_proj  (fp16 HMMA, 256x128 tiles)
    hmma_gemm_kernel<CC, 1><<<dim3(CC / 128, MM / 256), 256, GEMM_SMEM>>>(
        b_proj, out);
}

// round 15
// speedup vs baseline: 3.0303x; 1.1606x over previous
#include <cuda_runtime.h>
#include <cuda_bf16.h>
#include <cuda_fp16.h>
#include <cstdint>

// Problem constants
#define BB 2
#define TT 2048
#define CC 1024
#define HH 16
#define DD 64
#define MM (BB * TT)   // 4096 rows

// ---------------------------------------------------------------------------
// Device scratch (allocation-free per harness rules) — all fp16 single-plane
// ---------------------------------------------------------------------------
__device__ __half g_q16[(size_t)BB * HH * TT * DD];   // (b,h,t,d), 128B rows
__device__ __half g_k16[(size_t)BB * HH * TT * DD];
__device__ __half g_v16[(size_t)BB * HH * TT * DD];
__device__ __half g_x16 [(size_t)MM * CC];            // x   [M][K]
__device__ __half g_wa16[(size_t)3 * CC * CC];        // W_attn^T [N][K]
__device__ __half g_wp16[(size_t)CC * CC];            // W_proj^T [N][K]
__device__ __half g_a16 [(size_t)MM * CC];            // attention out [M][K]

// ---------------------------------------------------------------------------
// PTX helpers (sm_80+ portable: cp.async / ldmatrix / mma.sync)
// ---------------------------------------------------------------------------
__device__ __forceinline__ uint32_t smem_to_u32(const void* smem_ptr) {
    uint32_t addr;
    asm("{ .reg .u64 tmp; cvta.to.shared.u64 tmp, %1; cvt.u32.u64 %0, tmp; }"
        : "=r"(addr) : "l"(smem_ptr));
    return addr;
}

__device__ __forceinline__ void cpasync16(uint32_t s, const void* g) {
    asm volatile("cp.async.cg.shared.global [%0], [%1], 16;" :: "r"(s), "l"(g) : "memory");
}

#define CP_COMMIT()  asm volatile("cp.async.commit_group;" ::: "memory")
#define CP_WAIT(n)   asm volatile("cp.async.wait_group %0;" :: "n"(n) : "memory")

#define LDSM_X4(r, addr) \
    asm volatile("ldmatrix.sync.aligned.m8n8.x4.shared.b16 {%0,%1,%2,%3}, [%4];" \
        : "=r"((r)[0]), "=r"((r)[1]), "=r"((r)[2]), "=r"((r)[3]) : "r"(addr))

#define LDSM_X4_T(r, addr) \
    asm volatile("ldmatrix.sync.aligned.m8n8.x4.trans.shared.b16 {%0,%1,%2,%3}, [%4];" \
        : "=r"((r)[0]), "=r"((r)[1]), "=r"((r)[2]), "=r"((r)[3]) : "r"(addr))

#define MMA_FP16(c, a, b0, b1) \
    asm volatile("mma.sync.aligned.m16n8k16.row.col.f32.f16.f16.f32 " \
        "{%0,%1,%2,%3}, {%4,%5,%6,%7}, {%8,%9}, {%0,%1,%2,%3};" \
        : "+f"((c)[0]), "+f"((c)[1]), "+f"((c)[2]), "+f"((c)[3]) \
        : "r"((a)[0]), "r"((a)[1]), "r"((a)[2]), "r"((a)[3]), "r"(b0), "r"(b1))

// hardware exp2 (MUFU.EX2): 1 instruction, rel err ~2^-22, -inf -> 0
__device__ __forceinline__ float fexp2(float x) {
    float y;
    asm("ex2.approx.ftz.f32 %0, %1;" : "=f"(y) : "f"(x));
    return y;
}

__device__ __forceinline__ uint32_t pack2h(float x, float y) {
    __half2 v = __floats2half2_rn(x, y);
    return *(uint32_t*)&v;
}

// ---------------------------------------------------------------------------
// Preprocessing
// ---------------------------------------------------------------------------
__global__ __launch_bounds__(256) void split_x_kernel(const float* __restrict__ x) {
    size_t i = (size_t)blockIdx.x * 256 + threadIdx.x;   // MM*CC/4 float4s
    float4 v = ((const float4*)x)[i];
    uint2 o;
    o.x = pack2h(v.x, v.y);
    o.y = pack2h(v.z, v.w);
    *(uint2*)(g_x16 + i * 4) = o;
}

// Transpose: W [K=1024][NN] fp32 -> Wt fp16 [NN][1024]
template <int NN, int WHICH>
__global__ __launch_bounds__(256) void tsplit_w_kernel(const float* __restrict__ W) {
    __shared__ float tile[32][33];
    __half* Wd = (WHICH == 0) ? g_wa16 : g_wp16;
    const int nb = blockIdx.x * 32;
    const int kb = blockIdx.y * 32;
    const int tx = threadIdx.x, ty = threadIdx.y;
#pragma unroll
    for (int r = 0; r < 4; ++r)
        tile[ty + r * 8][tx] = W[(size_t)(kb + ty + r * 8) * NN + nb + tx];
    __syncthreads();
#pragma unroll
    for (int r = 0; r < 4; ++r) {
        const int n = nb + ty + r * 8;
        const int k = kb + tx;
        Wd[(size_t)n * 1024 + k] = __float2half(tile[tx][ty + r * 8]);
    }
}

// ---------------------------------------------------------------------------
// fp16 tensor-core GEMM (exact R12 config — proven 99.6us QKV):
// CTA tile 128x128, K-chunk 32 fp16 (64B rows, xor swizzle ch^((row>>1)&3)),
// 3-stage cp.async pipeline, one __syncthreads per iteration, 2 CTAs/SM.
// 8 warps as 2(m) x 4(n); warp tile 64x32. SMEM stage 16KB: A@0, B@8192.
// MODE 0: scatter q/k/v fp16.  MODE 1: att -> Out fp32.
// ---------------------------------------------------------------------------
template <int Ndim, int MODE>
__global__ __launch_bounds__(256, 2) void hmma_gemm_kernel(
    const float* __restrict__ bias, float* __restrict__ Out)
{
    extern __shared__ __align__(1024) char smem[];
    const uint32_t sbase = smem_to_u32(smem);
    const int tid = threadIdx.x;
    const int lane = tid & 31;
    const int wid = tid >> 5;
    const int wm = wid >> 2;
    const int wn = wid & 3;
    const int m0 = blockIdx.y * 128;
    const int n0 = blockIdx.x * 128;
    constexpr int KT = 32;

    const __half* Aop = (MODE == 0) ? g_x16 : g_a16;
    const __half* Bop = (MODE == 0) ? g_wa16 : g_wp16;

    const char* gA = (const char*)Aop + (size_t)m0 * 2048;  // row = 1024 fp16 = 2048B
    const char* gB = (const char*)Bop + (size_t)n0 * 2048;

    float acc[4][4][4];
#pragma unroll
    for (int mf = 0; mf < 4; ++mf)
#pragma unroll
        for (int nf = 0; nf < 4; ++nf)
#pragma unroll
            for (int e = 0; e < 4; ++e) acc[mf][nf][e] = 0.f;

    auto issue = [&](int c) {
        const uint32_t tb = sbase + (uint32_t)(c % 3) * 16384;
        const int kb = c * 64;
#pragma unroll
        for (int i = 0; i < 2; ++i) {
            const int idx = tid + i * 256;
            const int row = idx >> 2;
            const int ch = idx & 3;
            const uint32_t soff = row * 64 + ((ch ^ ((row >> 1) & 3)) << 4);
            const size_t goff = (size_t)row * 2048 + ch * 16 + kb;
            cpasync16(tb + 0    + soff, gA + goff);
            cpasync16(tb + 8192 + soff, gB + goff);
        }
        CP_COMMIT();
    };

    issue(0);
    issue(1);

    const int q8 = lane >> 3;
    const int iq = lane & 7;
    const int rowoff_a = ((q8 & 1) << 3) + iq;
    const int khalf = q8 >> 1;

    for (int c = 0; c < KT; ++c) {
        CP_WAIT(1);
        __syncthreads();
        if (c + 2 < KT) issue(c + 2);

        const uint32_t tb = sbase + (uint32_t)(c % 3) * 16384;

#pragma unroll
        for (int ks = 0; ks < 2; ++ks) {
            const int cch = ks * 2 + khalf;
            uint32_t af[4][4];
#pragma unroll
            for (int mf = 0; mf < 4; ++mf) {
                const int row = wm * 64 + mf * 16 + rowoff_a;
                const uint32_t off = row * 64 + ((cch ^ ((row >> 1) & 3)) << 4);
                LDSM_X4(af[mf], tb + off);
            }
#pragma unroll
            for (int np = 0; np < 2; ++np) {
                const int row = wn * 32 + np * 16 + rowoff_a;
                const uint32_t off = row * 64 + ((cch ^ ((row >> 1) & 3)) << 4);
                uint32_t r[4];
                LDSM_X4(r, tb + 8192 + off);
                const int nf0 = 2 * np, nf1 = 2 * np + 1;
#pragma unroll
                for (int mf = 0; mf < 4; ++mf) {
                    MMA_FP16(acc[mf][nf0], af[mf], r[0], r[2]);
                    MMA_FP16(acc[mf][nf1], af[mf], r[1], r[3]);
                }
            }
        }
    }

    // Epilogue. Frag map: c0,c1 -> (row g, cols 2t,2t+1); c2,c3 -> row g+8.
    const int g = lane >> 2, t = lane & 3;
#pragma unroll
    for (int mf = 0; mf < 4; ++mf) {
        const int r_lo = m0 + wm * 64 + mf * 16 + g;
#pragma unroll
        for (int nf = 0; nf < 4; ++nf) {
            const int col = n0 + wn * 32 + nf * 8 + 2 * t;
            const float b0 = bias[col], b1 = bias[col + 1];
            float v00 = acc[mf][nf][0] + b0, v01 = acc[mf][nf][1] + b1;
            float v10 = acc[mf][nf][2] + b0, v11 = acc[mf][nf][3] + b1;
            if (MODE == 0) {
                const int which = col >> 10;
                const int ci = col & 1023;
                const int hh = ci >> 6;
                const int dd = ci & 63;
                __half* dst = (which == 0) ? g_q16 : ((which == 1) ? g_k16 : g_v16);
                const int b_lo = r_lo >> 11, t_lo = r_lo & 2047;
                const int r_hi = r_lo + 8;
                const int b_hi = r_hi >> 11, t_hi = r_hi & 2047;
                size_t off0 = (((size_t)b_lo * HH + hh) * TT + t_lo) * DD + dd;
                size_t off1 = (((size_t)b_hi * HH + hh) * TT + t_hi) * DD + dd;
                *(uint32_t*)(dst + off0) = pack2h(v00, v01);
                *(uint32_t*)(dst + off1) = pack2h(v10, v11);
            } else {
                *(float2*)(Out + (size_t)r_lo * Ndim + col) = float2{v00, v01};
                *(float2*)(Out + (size_t)(r_lo + 8) * Ndim + col) = float2{v10, v11};
            }
        }
    }
}

// ---------------------------------------------------------------------------
// Tensor-core flash attention, all-fp16 MMAs, 128-thread CTAs (64 q-rows),
// hardware MUFU.EX2 for all exponentials (was 9-instr FMA polynomial).
// SMEM: Q @0 (8KB); KV buffers @8192 + buf*16384: K@0 V@8192.
// ---------------------------------------------------------------------------
__global__ __launch_bounds__(128, 3) void attn_mma_kernel(const float* __restrict__ temp)
{
    extern __shared__ __align__(1024) char smem[];
    const uint32_t sb = smem_to_u32(smem);
    const int tid = threadIdx.x;
    const int lane = tid & 31;
    const int wid = tid >> 5;          // 0..3
    const int bh = blockIdx.y;
    const int qt = (int)gridDim.x - 1 - blockIdx.x;   // heavy tiles first
    const int b = bh >> 4;
    const int h = bh & 15;

    const float qscale = 0.125f * (1.0f / temp[0]) * 1.44269504088896340736f;
    const float slope = fexp2(-0.5f * (float)(h + 1)) * 1.44269504088896340736f;

    const int q8 = lane >> 3;
    const int iq = lane & 7;
    const int rowoff = ((q8 & 1) << 3) + iq;
    const int khalf = q8 >> 1;
    const int g = lane >> 2, t = lane & 3;

    const char* gQ = (const char*)g_q16 + ((size_t)bh * TT + qt * 64) * 128;
    const char* gK = (const char*)g_k16 + (size_t)bh * TT * 128;
    const char* gV = (const char*)g_v16 + (size_t)bh * TT * 128;

    const int nkt = qt + 1;   // 64-key tiles (causal)

    // stage Q (8KB: 64 rows x 128B)
#pragma unroll
    for (int i = 0; i < 4; ++i) {
        const int idx = tid + i * 128;
        const int row = idx >> 3;
        const int ch = idx & 7;
        const uint32_t soff = row * 128 + ((ch ^ (row & 7)) << 4);
        cpasync16(sb + soff, gQ + (size_t)row * 128 + ch * 16);
    }
    CP_COMMIT();

    auto issue_kv = [&](int kt) {
        const uint32_t tb = sb + 8192 + (uint32_t)(kt & 1) * 16384;
        const size_t kbase = (size_t)kt * 64 * 128;
#pragma unroll
        for (int i = 0; i < 4; ++i) {
            const int idx = tid + i * 128;
            const int row = idx >> 3;
            const int ch = idx & 7;
            const uint32_t soff = row * 128 + ((ch ^ (row & 7)) << 4);
            const size_t goff = kbase + (size_t)row * 128 + ch * 16;
            cpasync16(tb + 0    + soff, gK + goff);
            cpasync16(tb + 8192 + soff, gV + goff);
        }
        CP_COMMIT();
    };

    issue_kv(0);
    CP_WAIT(1);
    __syncthreads();

    // Q fragments resident (4 k16-steps; warp owns rows wid*16..wid*16+15)
    uint32_t qf[4][4];
#pragma unroll
    for (int ks = 0; ks < 4; ++ks) {
        const int row = wid * 16 + rowoff;
        const int cch = ks * 2 + khalf;
        const uint32_t off = row * 128 + ((cch ^ (row & 7)) << 4);
        LDSM_X4(qf[ks], sb + off);
    }

    float oacc[8][4];
#pragma unroll
    for (int nd = 0; nd < 8; ++nd)
#pragma unroll
        for (int e = 0; e < 4; ++e) oacc[nd][e] = 0.f;
    float m0 = -1e30f, m1 = -1e30f, l0 = 0.f, l1 = 0.f;

    const int qrow0 = qt * 64 + wid * 16 + g;
    const int qrow1 = qrow0 + 8;

    for (int kt = 0; kt < nkt; ++kt) {
        if (kt + 1 < nkt) { issue_kv(kt + 1); CP_WAIT(1); }
        else              { CP_WAIT(0); }
        __syncthreads();

        const uint32_t tb = sb + 8192 + (uint32_t)(kt & 1) * 16384;

        // ---- S = Q K^T (fp16) ----
        float sacc[8][4];
#pragma unroll
        for (int nf = 0; nf < 8; ++nf)
#pragma unroll
            for (int e = 0; e < 4; ++e) sacc[nf][e] = 0.f;

#pragma unroll
        for (int ks = 0; ks < 4; ++ks) {
            const int cch = ks * 2 + khalf;
#pragma unroll
            for (int np = 0; np < 4; ++np) {
                const int row = np * 16 + rowoff;
                const uint32_t off = row * 128 + ((cch ^ (row & 7)) << 4);
                uint32_t r[4];
                LDSM_X4(r, tb + off);
                MMA_FP16(sacc[2 * np],     qf[ks], r[0], r[2]);
                MMA_FP16(sacc[2 * np + 1], qf[ks], r[1], r[3]);
            }
        }

        // ---- softmax (online) ----
        const bool maskt = (kt == qt);
        float mx0 = -1e30f, mx1 = -1e30f;
#pragma unroll
        for (int nf = 0; nf < 8; ++nf) {
            const int key = kt * 64 + nf * 8 + 2 * t;
            float s0 = fmaf(sacc[nf][0], qscale, slope * (float)(key - qrow0));
            float s1 = fmaf(sacc[nf][1], qscale, slope * (float)(key + 1 - qrow0));
            float s2 = fmaf(sacc[nf][2], qscale, slope * (float)(key - qrow1));
            float s3 = fmaf(sacc[nf][3], qscale, slope * (float)(key + 1 - qrow1));
            if (maskt) {
                if (key > qrow0) s0 = -1e30f;
                if (key + 1 > qrow0) s1 = -1e30f;
                if (key > qrow1) s2 = -1e30f;
                if (key + 1 > qrow1) s3 = -1e30f;
            }
            sacc[nf][0] = s0; sacc[nf][1] = s1; sacc[nf][2] = s2; sacc[nf][3] = s3;
            mx0 = fmaxf(mx0, fmaxf(s0, s1));
            mx1 = fmaxf(mx1, fmaxf(s2, s3));
        }
        mx0 = fmaxf(mx0, __shfl_xor_sync(0xFFFFFFFFu, mx0, 1));
        mx0 = fmaxf(mx0, __shfl_xor_sync(0xFFFFFFFFu, mx0, 2));
        mx1 = fmaxf(mx1, __shfl_xor_sync(0xFFFFFFFFu, mx1, 1));
        mx1 = fmaxf(mx1, __shfl_xor_sync(0xFFFFFFFFu, mx1, 2));

        const float mn0 = fmaxf(m0, mx0);
        const float mn1 = fmaxf(m1, mx1);
        const float a0 = fexp2(m0 - mn0);
        const float a1 = fexp2(m1 - mn1);
        m0 = mn0; m1 = mn1;
        l0 *= a0; l1 *= a1;
#pragma unroll
        for (int nd = 0; nd < 8; ++nd) {
            oacc[nd][0] *= a0; oacc[nd][1] *= a0;
            oacc[nd][2] *= a1; oacc[nd][3] *= a1;
        }

        float rs0 = 0.f, rs1 = 0.f;
#pragma unroll
        for (int nf = 0; nf < 8; ++nf) {
            float p0 = fexp2(sacc[nf][0] - m0);
            float p1 = fexp2(sacc[nf][1] - m0);
            float p2 = fexp2(sacc[nf][2] - m1);
            float p3 = fexp2(sacc[nf][3] - m1);
            rs0 += p0 + p1; rs1 += p2 + p3;
            sacc[nf][0] = p0; sacc[nf][1] = p1; sacc[nf][2] = p2; sacc[nf][3] = p3;
        }
        rs0 += __shfl_xor_sync(0xFFFFFFFFu, rs0, 1);
        rs0 += __shfl_xor_sync(0xFFFFFFFFu, rs0, 2);
        rs1 += __shfl_xor_sync(0xFFFFFFFFu, rs1, 1);
        rs1 += __shfl_xor_sync(0xFFFFFFFFu, rs1, 2);
        l0 += rs0; l1 += rs1;

        // ---- pack P to fp16 A-frags ----
        uint32_t pa[4][4];
#pragma unroll
        for (int jp = 0; jp < 4; ++jp) {
            const int j0 = 2 * jp, j1 = 2 * jp + 1;
            pa[jp][0] = pack2h(sacc[j0][0], sacc[j0][1]);
            pa[jp][1] = pack2h(sacc[j0][2], sacc[j0][3]);
            pa[jp][2] = pack2h(sacc[j1][0], sacc[j1][1]);
            pa[jp][3] = pack2h(sacc[j1][2], sacc[j1][3]);
        }

        // ---- O += P V (fp16) ----
#pragma unroll
        for (int jp = 0; jp < 4; ++jp) {
            uint32_t vb[8][2];
#pragma unroll
            for (int p = 0; p < 4; ++p) {
                const int row = jp * 16 + rowoff;
                const int cch = 2 * p + khalf;
                const uint32_t off = row * 128 + ((cch ^ (row & 7)) << 4);
                uint32_t r[4];
                LDSM_X4_T(r, tb + 8192 + off);
                vb[2 * p][0] = r[0]; vb[2 * p][1] = r[1];
                vb[2 * p + 1][0] = r[2]; vb[2 * p + 1][1] = r[3];
            }
#pragma unroll
            for (int nd = 0; nd < 8; ++nd)
                MMA_FP16(oacc[nd], pa[jp], vb[nd][0], vb[nd][1]);
        }
        __syncthreads();
    }

    // epilogue: O /= l; write fp16 A operand for proj GEMM
    const float il0 = 1.0f / l0;
    const float il1 = 1.0f / l1;
    const size_t r0off = (size_t)(b * TT + qrow0) * CC + h * 64;
    const size_t r1off = (size_t)(b * TT + qrow1) * CC + h * 64;
#pragma unroll
    for (int nd = 0; nd < 8; ++nd) {
        const int cd = nd * 8 + 2 * t;
        *(uint32_t*)(g_a16 + r0off + cd) = pack2h(oacc[nd][0] * il0, oacc[nd][1] * il0);
        *(uint32_t*)(g_a16 + r1off + cd) = pack2h(oacc[nd][2] * il1, oacc[nd][3] * il1);
    }
}

// ---------------------------------------------------------------------------
// Harness entry
// ---------------------------------------------------------------------------
extern "C" void kernel_launch(void* const* d_in, const int* in_sizes, int n_in,
                              void* d_out, int out_size)
{
    const float* x      = (const float*)d_in[0];
    const float* W_attn = (const float*)d_in[1];
    const float* b_attn = (const float*)d_in[2];
    const float* W_proj = (const float*)d_in[3];
    const float* b_proj = (const float*)d_in[4];
    const float* temp   = (const float*)d_in[5];
    float* out = (float*)d_out;

    const int GEMM_SMEM = 3 * 16384;            // 49152 (2 CTAs/SM)
    const int ATTN_SMEM = 8192 + 2 * 16384;     // 40960 (3 CTAs/SM)
    cudaFuncSetAttribute(hmma_gemm_kernel<3 * CC, 0>,
                         cudaFuncAttributeMaxDynamicSharedMemorySize, GEMM_SMEM);
    cudaFuncSetAttribute(hmma_gemm_kernel<CC, 1>,
                         cudaFuncAttributeMaxDynamicSharedMemorySize, GEMM_SMEM);
    cudaFuncSetAttribute(attn_mma_kernel,
                         cudaFuncAttributeMaxDynamicSharedMemorySize, ATTN_SMEM);

    // 0) fp16 conversions (x) + weight transposes
    split_x_kernel<<<(MM * CC / 4) / 256, 256>>>(x);
    tsplit_w_kernel<3 * CC, 0><<<dim3(3 * CC / 32, CC / 32), dim3(32, 8)>>>(W_attn);
    tsplit_w_kernel<CC, 1><<<dim3(CC / 32, CC / 32), dim3(32, 8)>>>(W_proj);

    // 1) QKV = x @ W_attn + b_attn  (fp16 HMMA, 128x128 tiles, 2 CTAs/SM)
    hmma_gemm_kernel<3 * CC, 0><<<dim3(3 * CC / 128, MM / 128), 256, GEMM_SMEM>>>(
        b_attn, nullptr);

    // 2) tensor-core causal ALiBi attention (128-thread CTAs, MUFU exp)
    attn_mma_kernel<<<dim3(TT / 64, BB * HH), 128, ATTN_SMEM>>>(temp);

    // 3) out = att @ W_proj + b_proj  (fp16 HMMA, 128x128 tiles)
    hmma_gemm_kernel<CC, 1><<<dim3(CC / 128, MM / 128), 256, GEMM_SMEM>>>(
        b_proj, out);
}

// round 16
// speedup vs baseline: 3.0520x; 1.0072x over previous
#include <cuda_runtime.h>
#include <cuda_bf16.h>
#include <cuda_fp16.h>
#include <cstdint>

// Problem constants
#define BB 2
#define TT 2048
#define CC 1024
#define HH 16
#define DD 64
#define MM (BB * TT)   // 4096 rows

// ---------------------------------------------------------------------------
// Device scratch (allocation-free per harness rules) — all fp16 single-plane
// ---------------------------------------------------------------------------
__device__ __half g_q16[(size_t)BB * HH * TT * DD];   // (b,h,t,d), 128B rows
__device__ __half g_k16[(size_t)BB * HH * TT * DD];
__device__ __half g_v16[(size_t)BB * HH * TT * DD];
__device__ __half g_x16 [(size_t)MM * CC];            // x   [M][K]
__device__ __half g_wa16[(size_t)3 * CC * CC];        // W_attn^T [N][K]
__device__ __half g_wp16[(size_t)CC * CC];            // W_proj^T [N][K]
__device__ __half g_a16 [(size_t)MM * CC];            // attention out [M][K]

// ---------------------------------------------------------------------------
// PTX helpers (sm_80+ portable: cp.async / ldmatrix / mma.sync)
// ---------------------------------------------------------------------------
__device__ __forceinline__ uint32_t smem_to_u32(const void* smem_ptr) {
    uint32_t addr;
    asm("{ .reg .u64 tmp; cvta.to.shared.u64 tmp, %1; cvt.u32.u64 %0, tmp; }"
        : "=r"(addr) : "l"(smem_ptr));
    return addr;
}

__device__ __forceinline__ void cpasync16(uint32_t s, const void* g) {
    asm volatile("cp.async.cg.shared.global [%0], [%1], 16;" :: "r"(s), "l"(g) : "memory");
}

#define CP_COMMIT()  asm volatile("cp.async.commit_group;" ::: "memory")
#define CP_WAIT(n)   asm volatile("cp.async.wait_group %0;" :: "n"(n) : "memory")

#define LDSM_X4(r, addr) \
    asm volatile("ldmatrix.sync.aligned.m8n8.x4.shared.b16 {%0,%1,%2,%3}, [%4];" \
        : "=r"((r)[0]), "=r"((r)[1]), "=r"((r)[2]), "=r"((r)[3]) : "r"(addr))

#define LDSM_X4_T(r, addr) \
    asm volatile("ldmatrix.sync.aligned.m8n8.x4.trans.shared.b16 {%0,%1,%2,%3}, [%4];" \
        : "=r"((r)[0]), "=r"((r)[1]), "=r"((r)[2]), "=r"((r)[3]) : "r"(addr))

#define MMA_FP16(c, a, b0, b1) \
    asm volatile("mma.sync.aligned.m16n8k16.row.col.f32.f16.f16.f32 " \
        "{%0,%1,%2,%3}, {%4,%5,%6,%7}, {%8,%9}, {%0,%1,%2,%3};" \
        : "+f"((c)[0]), "+f"((c)[1]), "+f"((c)[2]), "+f"((c)[3]) \
        : "r"((a)[0]), "r"((a)[1]), "r"((a)[2]), "r"((a)[3]), "r"(b0), "r"(b1))

// hardware exp2 (MUFU.EX2): 1 instruction, rel err ~2^-22, -inf -> 0
__device__ __forceinline__ float fexp2(float x) {
    float y;
    asm("ex2.approx.ftz.f32 %0, %1;" : "=f"(y) : "f"(x));
    return y;
}

__device__ __forceinline__ uint32_t pack2h(float x, float y) {
    __half2 v = __floats2half2_rn(x, y);
    return *(uint32_t*)&v;
}

// ---------------------------------------------------------------------------
// Preprocessing
// ---------------------------------------------------------------------------
__global__ __launch_bounds__(256) void split_x_kernel(const float* __restrict__ x) {
    size_t i = (size_t)blockIdx.x * 256 + threadIdx.x;   // MM*CC/4 float4s
    float4 v = ((const float4*)x)[i];
    uint2 o;
    o.x = pack2h(v.x, v.y);
    o.y = pack2h(v.z, v.w);
    *(uint2*)(g_x16 + i * 4) = o;
}

// Transpose: W [K=1024][NN] fp32 -> Wt fp16 [NN][1024]
template <int NN, int WHICH>
__global__ __launch_bounds__(256) void tsplit_w_kernel(const float* __restrict__ W) {
    __shared__ float tile[32][33];
    __half* Wd = (WHICH == 0) ? g_wa16 : g_wp16;
    const int nb = blockIdx.x * 32;
    const int kb = blockIdx.y * 32;
    const int tx = threadIdx.x, ty = threadIdx.y;
#pragma unroll
    for (int r = 0; r < 4; ++r)
        tile[ty + r * 8][tx] = W[(size_t)(kb + ty + r * 8) * NN + nb + tx];
    __syncthreads();
#pragma unroll
    for (int r = 0; r < 4; ++r) {
        const int n = nb + ty + r * 8;
        const int k = kb + tx;
        Wd[(size_t)n * 1024 + k] = __float2half(tile[tx][ty + r * 8]);
    }
}

// ---------------------------------------------------------------------------
// fp16 tensor-core GEMM: C = A[M,K] @ Wt[N,K]^T + bias
// CTA tile 128x128, 128 threads, 4 warps as 2(m) x 2(n); warp tile 64x64
// (4 m-frags x 8 n-frags). Crossbar duplication A x2 + B x2 = 32KB/chunk
// (was 48KB with the 8-warp 2x4 layout). K-chunk 32 fp16, xor swizzle,
// 3-stage cp.async pipeline, one __syncthreads per iteration.
// SMEM stage 16KB: A@0 (8KB), B@8192 (8KB).
// MODE 0: scatter q/k/v fp16.  MODE 1: att -> Out fp32.
// ---------------------------------------------------------------------------
template <int Ndim, int MODE>
__global__ __launch_bounds__(128, 2) void hmma_gemm_kernel(
    const float* __restrict__ bias, float* __restrict__ Out)
{
    extern __shared__ __align__(1024) char smem[];
    const uint32_t sbase = smem_to_u32(smem);
    const int tid = threadIdx.x;
    const int lane = tid & 31;
    const int wid = tid >> 5;   // 0..3
    const int wm = wid >> 1;    // 0..1
    const int wn = wid & 1;     // 0..1
    const int m0 = blockIdx.y * 128;
    const int n0 = blockIdx.x * 128;
    constexpr int KT = 32;

    const __half* Aop = (MODE == 0) ? g_x16 : g_a16;
    const __half* Bop = (MODE == 0) ? g_wa16 : g_wp16;

    const char* gA = (const char*)Aop + (size_t)m0 * 2048;  // row = 1024 fp16 = 2048B
    const char* gB = (const char*)Bop + (size_t)n0 * 2048;

    float acc[4][8][4];
#pragma unroll
    for (int mf = 0; mf < 4; ++mf)
#pragma unroll
        for (int nf = 0; nf < 8; ++nf)
#pragma unroll
            for (int e = 0; e < 4; ++e) acc[mf][nf][e] = 0.f;

    // stage = 16KB; each plane 8KB = 512 x 16B chunks; 128 threads x 4 each
    auto issue = [&](int c) {
        const uint32_t tb = sbase + (uint32_t)(c % 3) * 16384;
        const int kb = c * 64;
#pragma unroll
        for (int i = 0; i < 4; ++i) {
            const int idx = tid + i * 128;
            const int row = idx >> 2;           // 0..127
            const int ch = idx & 3;
            const uint32_t soff = row * 64 + ((ch ^ ((row >> 1) & 3)) << 4);
            const size_t goff = (size_t)row * 2048 + ch * 16 + kb;
            cpasync16(tb + 0    + soff, gA + goff);
            cpasync16(tb + 8192 + soff, gB + goff);
        }
        CP_COMMIT();
    };

    issue(0);
    issue(1);

    const int q8 = lane >> 3;
    const int iq = lane & 7;
    const int rowoff_a = ((q8 & 1) << 3) + iq;
    const int khalf = q8 >> 1;

    for (int c = 0; c < KT; ++c) {
        CP_WAIT(1);
        __syncthreads();
        if (c + 2 < KT) issue(c + 2);

        const uint32_t tb = sbase + (uint32_t)(c % 3) * 16384;

#pragma unroll
        for (int ks = 0; ks < 2; ++ks) {
            const int cch = ks * 2 + khalf;
            uint32_t af[4][4];
#pragma unroll
            for (int mf = 0; mf < 4; ++mf) {
                const int row = wm * 64 + mf * 16 + rowoff_a;
                const uint32_t off = row * 64 + ((cch ^ ((row >> 1) & 3)) << 4);
                LDSM_X4(af[mf], tb + off);
            }
#pragma unroll
            for (int np = 0; np < 4; ++np) {
                const int row = wn * 64 + np * 16 + rowoff_a;
                const uint32_t off = row * 64 + ((cch ^ ((row >> 1) & 3)) << 4);
                uint32_t r[4];
                LDSM_X4(r, tb + 8192 + off);
                const int nf0 = 2 * np, nf1 = 2 * np + 1;
#pragma unroll
                for (int mf = 0; mf < 4; ++mf) {
                    MMA_FP16(acc[mf][nf0], af[mf], r[0], r[2]);
                    MMA_FP16(acc[mf][nf1], af[mf], r[1], r[3]);
                }
            }
        }
    }

    // Epilogue. Frag map: c0,c1 -> (row g, cols 2t,2t+1); c2,c3 -> row g+8.
    const int g = lane >> 2, t = lane & 3;
#pragma unroll
    for (int mf = 0; mf < 4; ++mf) {
        const int r_lo = m0 + wm * 64 + mf * 16 + g;
#pragma unroll
        for (int nf = 0; nf < 8; ++nf) {
            const int col = n0 + wn * 64 + nf * 8 + 2 * t;
            const float b0 = bias[col], b1 = bias[col + 1];
            float v00 = acc[mf][nf][0] + b0, v01 = acc[mf][nf][1] + b1;
            float v10 = acc[mf][nf][2] + b0, v11 = acc[mf][nf][3] + b1;
            if (MODE == 0) {
                const int which = col >> 10;
                const int ci = col & 1023;
                const int hh = ci >> 6;
                const int dd = ci & 63;
                __half* dst = (which == 0) ? g_q16 : ((which == 1) ? g_k16 : g_v16);
                const int b_lo = r_lo >> 11, t_lo = r_lo & 2047;
                const int r_hi = r_lo + 8;
                const int b_hi = r_hi >> 11, t_hi = r_hi & 2047;
                size_t off0 = (((size_t)b_lo * HH + hh) * TT + t_lo) * DD + dd;
                size_t off1 = (((size_t)b_hi * HH + hh) * TT + t_hi) * DD + dd;
                *(uint32_t*)(dst + off0) = pack2h(v00, v01);
                *(uint32_t*)(dst + off1) = pack2h(v10, v11);
            } else {
                *(float2*)(Out + (size_t)r_lo * Ndim + col) = float2{v00, v01};
                *(float2*)(Out + (size_t)(r_lo + 8) * Ndim + col) = float2{v10, v11};
            }
        }
    }
}

// ---------------------------------------------------------------------------
// Tensor-core flash attention (unchanged from R14): all-fp16 MMAs,
// 128-thread CTAs (64 q-rows), MUFU.EX2 exponentials.
// SMEM: Q @0 (8KB); KV buffers @8192 + buf*16384: K@0 V@8192.
// ---------------------------------------------------------------------------
__global__ __launch_bounds__(128, 3) void attn_mma_kernel(const float* __restrict__ temp)
{
    extern __shared__ __align__(1024) char smem[];
    const uint32_t sb = smem_to_u32(smem);
    const int tid = threadIdx.x;
    const int lane = tid & 31;
    const int wid = tid >> 5;          // 0..3
    const int bh = blockIdx.y;
    const int qt = (int)gridDim.x - 1 - blockIdx.x;   // heavy tiles first
    const int b = bh >> 4;
    const int h = bh & 15;

    const float qscale = 0.125f * (1.0f / temp[0]) * 1.44269504088896340736f;
    const float slope = fexp2(-0.5f * (float)(h + 1)) * 1.44269504088896340736f;

    const int q8 = lane >> 3;
    const int iq = lane & 7;
    const int rowoff = ((q8 & 1) << 3) + iq;
    const int khalf = q8 >> 1;
    const int g = lane >> 2, t = lane & 3;

    const char* gQ = (const char*)g_q16 + ((size_t)bh * TT + qt * 64) * 128;
    const char* gK = (const char*)g_k16 + (size_t)bh * TT * 128;
    const char* gV = (const char*)g_v16 + (size_t)bh * TT * 128;

    const int nkt = qt + 1;   // 64-key tiles (causal)

    // stage Q (8KB: 64 rows x 128B)
#pragma unroll
    for (int i = 0; i < 4; ++i) {
        const int idx = tid + i * 128;
        const int row = idx >> 3;
        const int ch = idx & 7;
        const uint32_t soff = row * 128 + ((ch ^ (row & 7)) << 4);
        cpasync16(sb + soff, gQ + (size_t)row * 128 + ch * 16);
    }
    CP_COMMIT();

    auto issue_kv = [&](int kt) {
        const uint32_t tb = sb + 8192 + (uint32_t)(kt & 1) * 16384;
        const size_t kbase = (size_t)kt * 64 * 128;
#pragma unroll
        for (int i = 0; i < 4; ++i) {
            const int idx = tid + i * 128;
            const int row = idx >> 3;
            const int ch = idx & 7;
            const uint32_t soff = row * 128 + ((ch ^ (row & 7)) << 4);
            const size_t goff = kbase + (size_t)row * 128 + ch * 16;
            cpasync16(tb + 0    + soff, gK + goff);
            cpasync16(tb + 8192 + soff, gV + goff);
        }
        CP_COMMIT();
    };

    issue_kv(0);
    CP_WAIT(1);
    __syncthreads();

    // Q fragments resident (4 k16-steps; warp owns rows wid*16..wid*16+15)
    uint32_t qf[4][4];
#pragma unroll
    for (int ks = 0; ks < 4; ++ks) {
        const int row = wid * 16 + rowoff;
        const int cch = ks * 2 + khalf;
        const uint32_t off = row * 128 + ((cch ^ (row & 7)) << 4);
        LDSM_X4(qf[ks], sb + off);
    }

    float oacc[8][4];
#pragma unroll
    for (int nd = 0; nd < 8; ++nd)
#pragma unroll
        for (int e = 0; e < 4; ++e) oacc[nd][e] = 0.f;
    float m0 = -1e30f, m1 = -1e30f, l0 = 0.f, l1 = 0.f;

    const int qrow0 = qt * 64 + wid * 16 + g;
    const int qrow1 = qrow0 + 8;

    for (int kt = 0; kt < nkt; ++kt) {
        if (kt + 1 < nkt) { issue_kv(kt + 1); CP_WAIT(1); }
        else              { CP_WAIT(0); }
        __syncthreads();

        const uint32_t tb = sb + 8192 + (uint32_t)(kt & 1) * 16384;

        // ---- S = Q K^T (fp16) ----
        float sacc[8][4];
#pragma unroll
        for (int nf = 0; nf < 8; ++nf)
#pragma unroll
            for (int e = 0; e < 4; ++e) sacc[nf][e] = 0.f;

#pragma unroll
        for (int ks = 0; ks < 4; ++ks) {
            const int cch = ks * 2 + khalf;
#pragma unroll
            for (int np = 0; np < 4; ++np) {
                const int row = np * 16 + rowoff;
                const uint32_t off = row * 128 + ((cch ^ (row & 7)) << 4);
                uint32_t r[4];
                LDSM_X4(r, tb + off);
                MMA_FP16(sacc[2 * np],     qf[ks], r[0], r[2]);
                MMA_FP16(sacc[2 * np + 1], qf[ks], r[1], r[3]);
            }
        }

        // ---- softmax (online) ----
        const bool maskt = (kt == qt);
        float mx0 = -1e30f, mx1 = -1e30f;
#pragma unroll
        for (int nf = 0; nf < 8; ++nf) {
            const int key = kt * 64 + nf * 8 + 2 * t;
            float s0 = fmaf(sacc[nf][0], qscale, slope * (float)(key - qrow0));
            float s1 = fmaf(sacc[nf][1], qscale, slope * (float)(key + 1 - qrow0));
            float s2 = fmaf(sacc[nf][2], qscale, slope * (float)(key - qrow1));
            float s3 = fmaf(sacc[nf][3], qscale, slope * (float)(key + 1 - qrow1));
            if (maskt) {
                if (key > qrow0) s0 = -1e30f;
                if (key + 1 > qrow0) s1 = -1e30f;
                if (key > qrow1) s2 = -1e30f;
                if (key + 1 > qrow1) s3 = -1e30f;
            }
            sacc[nf][0] = s0; sacc[nf][1] = s1; sacc[nf][2] = s2; sacc[nf][3] = s3;
            mx0 = fmaxf(mx0, fmaxf(s0, s1));
            mx1 = fmaxf(mx1, fmaxf(s2, s3));
        }
        mx0 = fmaxf(mx0, __shfl_xor_sync(0xFFFFFFFFu, mx0, 1));
        mx0 = fmaxf(mx0, __shfl_xor_sync(0xFFFFFFFFu, mx0, 2));
        mx1 = fmaxf(mx1, __shfl_xor_sync(0xFFFFFFFFu, mx1, 1));
        mx1 = fmaxf(mx1, __shfl_xor_sync(0xFFFFFFFFu, mx1, 2));

        const float mn0 = fmaxf(m0, mx0);
        const float mn1 = fmaxf(m1, mx1);
        const float a0 = fexp2(m0 - mn0);
        const float a1 = fexp2(m1 - mn1);
        m0 = mn0; m1 = mn1;
        l0 *= a0; l1 *= a1;
#pragma unroll
        for (int nd = 0; nd < 8; ++nd) {
            oacc[nd][0] *= a0; oacc[nd][1] *= a0;
            oacc[nd][2] *= a1; oacc[nd][3] *= a1;
        }

        float rs0 = 0.f, rs1 = 0.f;
#pragma unroll
        for (int nf = 0; nf < 8; ++nf) {
            float p0 = fexp2(sacc[nf][0] - m0);
            float p1 = fexp2(sacc[nf][1] - m0);
            float p2 = fexp2(sacc[nf][2] - m1);
            float p3 = fexp2(sacc[nf][3] - m1);
            rs0 += p0 + p1; rs1 += p2 + p3;
            sacc[nf][0] = p0; sacc[nf][1] = p1; sacc[nf][2] = p2; sacc[nf][3] = p3;
        }
        rs0 += __shfl_xor_sync(0xFFFFFFFFu, rs0, 1);
        rs0 += __shfl_xor_sync(0xFFFFFFFFu, rs0, 2);
        rs1 += __shfl_xor_sync(0xFFFFFFFFu, rs1, 1);
        rs1 += __shfl_xor_sync(0xFFFFFFFFu, rs1, 2);
        l0 += rs0; l1 += rs1;

        // ---- pack P to fp16 A-frags ----
        uint32_t pa[4][4];
#pragma unroll
        for (int jp = 0; jp < 4; ++jp) {
            const int j0 = 2 * jp, j1 = 2 * jp + 1;
            pa[jp][0] = pack2h(sacc[j0][0], sacc[j0][1]);
            pa[jp][1] = pack2h(sacc[j0][2], sacc[j0][3]);
            pa[jp][2] = pack2h(sacc[j1][0], sacc[j1][1]);
            pa[jp][3] = pack2h(sacc[j1][2], sacc[j1][3]);
        }

        // ---- O += P V (fp16) ----
#pragma unroll
        for (int jp = 0; jp < 4; ++jp) {
            uint32_t vb[8][2];
#pragma unroll
            for (int p = 0; p < 4; ++p) {
                const int row = jp * 16 + rowoff;
                const int cch = 2 * p + khalf;
                const uint32_t off = row * 128 + ((cch ^ (row & 7)) << 4);
                uint32_t r[4];
                LDSM_X4_T(r, tb + 8192 + off);
                vb[2 * p][0] = r[0]; vb[2 * p][1] = r[1];
                vb[2 * p + 1][0] = r[2]; vb[2 * p + 1][1] = r[3];
            }
#pragma unroll
            for (int nd = 0; nd < 8; ++nd)
                MMA_FP16(oacc[nd], pa[jp], vb[nd][0], vb[nd][1]);
        }
        __syncthreads();
    }

    // epilogue: O /= l; write fp16 A operand for proj GEMM
    const float il0 = 1.0f / l0;
    const float il1 = 1.0f / l1;
    const size_t r0off = (size_t)(b * TT + qrow0) * CC + h * 64;
    const size_t r1off = (size_t)(b * TT + qrow1) * CC + h * 64;
#pragma unroll
    for (int nd = 0; nd < 8; ++nd) {
        const int cd = nd * 8 + 2 * t;
        *(uint32_t*)(g_a16 + r0off + cd) = pack2h(oacc[nd][0] * il0, oacc[nd][1] * il0);
        *(uint32_t*)(g_a16 + r1off + cd) = pack2h(oacc[nd][2] * il1, oacc[nd][3] * il1);
    }
}

// ---------------------------------------------------------------------------
// Harness entry
// ---------------------------------------------------------------------------
extern "C" void kernel_launch(void* const* d_in, const int* in_sizes, int n_in,
                              void* d_out, int out_size)
{
    const float* x      = (const float*)d_in[0];
    const float* W_attn = (const float*)d_in[1];
    const float* b_attn = (const float*)d_in[2];
    const float* W_proj = (const float*)d_in[3];
    const float* b_proj = (const float*)d_in[4];
    const float* temp   = (const float*)d_in[5];
    float* out = (float*)d_out;

    const int GEMM_SMEM = 3 * 16384;            // 49152
    const int ATTN_SMEM = 8192 + 2 * 16384;     // 40960
    cudaFuncSetAttribute(hmma_gemm_kernel<3 * CC, 0>,
                         cudaFuncAttributeMaxDynamicSharedMemorySize, GEMM_SMEM);
    cudaFuncSetAttribute(hmma_gemm_kernel<CC, 1>,
                         cudaFuncAttributeMaxDynamicSharedMemorySize, GEMM_SMEM);
    cudaFuncSetAttribute(attn_mma_kernel,
                         cudaFuncAttributeMaxDynamicSharedMemorySize, ATTN_SMEM);

    // 0) fp16 conversions (x) + weight transposes
    split_x_kernel<<<(MM * CC / 4) / 256, 256>>>(x);
    tsplit_w_kernel<3 * CC, 0><<<dim3(3 * CC / 32, CC / 32), dim3(32, 8)>>>(W_attn);
    tsplit_w_kernel<CC, 1><<<dim3(CC / 32, CC / 32), dim3(32, 8)>>>(W_proj);

    // 1) QKV = x @ W_attn + b_attn  (fp16 HMMA, 4-warp 64x64 warp tiles)
    hmma_gemm_kernel<3 * CC, 0><<<dim3(3 * CC / 128, MM / 128), 128, GEMM_SMEM>>>(
        b_attn, nullptr);

    // 2) tensor-core causal ALiBi attention (128-thread CTAs, MUFU exp)
    attn_mma_kernel<<<dim3(TT / 64, BB * HH), 128, ATTN_SMEM>>>(temp);

    // 3) out = att @ W_proj + b_proj  (fp16 HMMA, 4-warp 64x64 warp tiles)
    hmma_gemm_kernel<CC, 1><<<dim3(CC / 128, MM / 128), 128, GEMM_SMEM>>>(
        b_proj, out);
}

// round 17
// speedup vs baseline: 3.1208x; 1.0225x over previous
#include <cuda_runtime.h>
#include <cuda_bf16.h>
#include <cuda_fp16.h>
#include <cstdint>

// Problem constants
#define BB 2
#define TT 2048
#define CC 1024
#define HH 16
#define DD 64
#define MM (BB * TT)   // 4096 rows

// ---------------------------------------------------------------------------
// Device scratch (allocation-free per harness rules) — all fp16 single-plane
// ---------------------------------------------------------------------------
__device__ __half g_q16[(size_t)BB * HH * TT * DD];   // (b,h,t,d), 128B rows
__device__ __half g_k16[(size_t)BB * HH * TT * DD];
__device__ __half g_v16[(size_t)BB * HH * TT * DD];
__device__ __half g_x16 [(size_t)MM * CC];            // x   [M][K]
__device__ __half g_wa16[(size_t)3 * CC * CC];        // W_attn^T [N][K]
__device__ __half g_wp16[(size_t)CC * CC];            // W_proj^T [N][K]
__device__ __half g_a16 [(size_t)MM * CC];            // attention out [M][K]

// ---------------------------------------------------------------------------
// PTX helpers (sm_80+ portable: cp.async / ldmatrix / mma.sync)
// ---------------------------------------------------------------------------
__device__ __forceinline__ uint32_t smem_to_u32(const void* smem_ptr) {
    uint32_t addr;
    asm("{ .reg .u64 tmp; cvta.to.shared.u64 tmp, %1; cvt.u32.u64 %0, tmp; }"
        : "=r"(addr) : "l"(smem_ptr));
    return addr;
}

__device__ __forceinline__ void cpasync16(uint32_t s, const void* g) {
    asm volatile("cp.async.cg.shared.global [%0], [%1], 16;" :: "r"(s), "l"(g) : "memory");
}

#define CP_COMMIT()  asm volatile("cp.async.commit_group;" ::: "memory")
#define CP_WAIT(n)   asm volatile("cp.async.wait_group %0;" :: "n"(n) : "memory")

#define LDSM_X4(r, addr) \
    asm volatile("ldmatrix.sync.aligned.m8n8.x4.shared.b16 {%0,%1,%2,%3}, [%4];" \
        : "=r"((r)[0]), "=r"((r)[1]), "=r"((r)[2]), "=r"((r)[3]) : "r"(addr))

#define LDSM_X4_T(r, addr) \
    asm volatile("ldmatrix.sync.aligned.m8n8.x4.trans.shared.b16 {%0,%1,%2,%3}, [%4];" \
        : "=r"((r)[0]), "=r"((r)[1]), "=r"((r)[2]), "=r"((r)[3]) : "r"(addr))

#define MMA_FP16(c, a, b0, b1) \
    asm volatile("mma.sync.aligned.m16n8k16.row.col.f32.f16.f16.f32 " \
        "{%0,%1,%2,%3}, {%4,%5,%6,%7}, {%8,%9}, {%0,%1,%2,%3};" \
        : "+f"((c)[0]), "+f"((c)[1]), "+f"((c)[2]), "+f"((c)[3]) \
        : "r"((a)[0]), "r"((a)[1]), "r"((a)[2]), "r"((a)[3]), "r"(b0), "r"(b1))

// hardware exp2 (MUFU.EX2): 1 instruction, rel err ~2^-22, -inf -> 0
__device__ __forceinline__ float fexp2(float x) {
    float y;
    asm("ex2.approx.ftz.f32 %0, %1;" : "=f"(y) : "f"(x));
    return y;
}

__device__ __forceinline__ uint32_t pack2h(float x, float y) {
    __half2 v = __floats2half2_rn(x, y);
    return *(uint32_t*)&v;
}

// ---------------------------------------------------------------------------
// Fused preprocessing: ONE launch covering
//   blocks [0, 4096)          : x fp32 -> fp16        (1 float4/thread)
//   blocks [4096, 7168)       : W_attn transpose+cvt  (32x32 tiles, 96 x 32)
//   blocks [7168, 8192)       : W_proj transpose+cvt  (32x32 tiles, 32 x 32)
// ---------------------------------------------------------------------------
__global__ __launch_bounds__(256) void prep_kernel(
    const float* __restrict__ x,
    const float* __restrict__ Wa,
    const float* __restrict__ Wp)
{
    const int bid = blockIdx.x;
    const int tid = threadIdx.x;

    if (bid < 4096) {
        // x convert: MM*CC = 4M floats = 1M float4s over 4096 blocks
        size_t i = (size_t)bid * 256 + tid;
        float4 v = ((const float4*)x)[i];
        uint2 o;
        o.x = pack2h(v.x, v.y);
        o.y = pack2h(v.z, v.w);
        *(uint2*)(g_x16 + i * 4) = o;
        return;
    }

    // transpose + convert (shared 32x33 tile, 256 threads as 32x8)
    __shared__ float tile[32][33];
    const int tx = tid & 31;
    const int ty = tid >> 5;   // 0..7

    const float* W;
    __half* Wd;
    int nb, kb, NN;
    if (bid < 4096 + 3072) {
        const int tb = bid - 4096;        // W_attn: 96 n-tiles x 32 k-tiles
        nb = (tb % 96) * 32;
        kb = (tb / 96) * 32;
        W = Wa; Wd = g_wa16; NN = 3 * CC;
    } else {
        const int tb = bid - 7168;        // W_proj: 32 x 32
        nb = (tb % 32) * 32;
        kb = (tb / 32) * 32;
        W = Wp; Wd = g_wp16; NN = CC;
    }

#pragma unroll
    for (int r = 0; r < 4; ++r)
        tile[ty + r * 8][tx] = W[(size_t)(kb + ty + r * 8) * NN + nb + tx];
    __syncthreads();
#pragma unroll
    for (int r = 0; r < 4; ++r) {
        const int n = nb + ty + r * 8;
        const int k = kb + tx;
        Wd[(size_t)n * 1024 + k] = __float2half(tile[tx][ty + r * 8]);
    }
}

// ---------------------------------------------------------------------------
// fp16 tensor-core GEMM (unchanged R15 config): C = A[M,K] @ Wt[N,K]^T + bias
// CTA tile 128x128, 128 threads, 4 warps as 2(m) x 2(n); warp tile 64x64.
// K-chunk 32 fp16, xor swizzle, 3-stage cp.async pipeline.
// SMEM stage 16KB: A@0 (8KB), B@8192 (8KB).
// MODE 0: scatter q/k/v fp16.  MODE 1: att -> Out fp32.
// ---------------------------------------------------------------------------
template <int Ndim, int MODE>
__global__ __launch_bounds__(128, 2) void hmma_gemm_kernel(
    const float* __restrict__ bias, float* __restrict__ Out)
{
    extern __shared__ __align__(1024) char smem[];
    const uint32_t sbase = smem_to_u32(smem);
    const int tid = threadIdx.x;
    const int lane = tid & 31;
    const int wid = tid >> 5;   // 0..3
    const int wm = wid >> 1;    // 0..1
    const int wn = wid & 1;     // 0..1
    const int m0 = blockIdx.y * 128;
    const int n0 = blockIdx.x * 128;
    constexpr int KT = 32;

    const __half* Aop = (MODE == 0) ? g_x16 : g_a16;
    const __half* Bop = (MODE == 0) ? g_wa16 : g_wp16;

    const char* gA = (const char*)Aop + (size_t)m0 * 2048;  // row = 1024 fp16 = 2048B
    const char* gB = (const char*)Bop + (size_t)n0 * 2048;

    float acc[4][8][4];
#pragma unroll
    for (int mf = 0; mf < 4; ++mf)
#pragma unroll
        for (int nf = 0; nf < 8; ++nf)
#pragma unroll
            for (int e = 0; e < 4; ++e) acc[mf][nf][e] = 0.f;

    auto issue = [&](int c) {
        const uint32_t tb = sbase + (uint32_t)(c % 3) * 16384;
        const int kb = c * 64;
#pragma unroll
        for (int i = 0; i < 4; ++i) {
            const int idx = tid + i * 128;
            const int row = idx >> 2;           // 0..127
            const int ch = idx & 3;
            const uint32_t soff = row * 64 + ((ch ^ ((row >> 1) & 3)) << 4);
            const size_t goff = (size_t)row * 2048 + ch * 16 + kb;
            cpasync16(tb + 0    + soff, gA + goff);
            cpasync16(tb + 8192 + soff, gB + goff);
        }
        CP_COMMIT();
    };

    issue(0);
    issue(1);

    const int q8 = lane >> 3;
    const int iq = lane & 7;
    const int rowoff_a = ((q8 & 1) << 3) + iq;
    const int khalf = q8 >> 1;

    for (int c = 0; c < KT; ++c) {
        CP_WAIT(1);
        __syncthreads();
        if (c + 2 < KT) issue(c + 2);

        const uint32_t tb = sbase + (uint32_t)(c % 3) * 16384;

#pragma unroll
        for (int ks = 0; ks < 2; ++ks) {
            const int cch = ks * 2 + khalf;
            uint32_t af[4][4];
#pragma unroll
            for (int mf = 0; mf < 4; ++mf) {
                const int row = wm * 64 + mf * 16 + rowoff_a;
                const uint32_t off = row * 64 + ((cch ^ ((row >> 1) & 3)) << 4);
                LDSM_X4(af[mf], tb + off);
            }
#pragma unroll
            for (int np = 0; np < 4; ++np) {
                const int row = wn * 64 + np * 16 + rowoff_a;
                const uint32_t off = row * 64 + ((cch ^ ((row >> 1) & 3)) << 4);
                uint32_t r[4];
                LDSM_X4(r, tb + 8192 + off);
                const int nf0 = 2 * np, nf1 = 2 * np + 1;
#pragma unroll
                for (int mf = 0; mf < 4; ++mf) {
                    MMA_FP16(acc[mf][nf0], af[mf], r[0], r[2]);
                    MMA_FP16(acc[mf][nf1], af[mf], r[1], r[3]);
                }
            }
        }
    }

    // Epilogue. Frag map: c0,c1 -> (row g, cols 2t,2t+1); c2,c3 -> row g+8.
    const int g = lane >> 2, t = lane & 3;
#pragma unroll
    for (int mf = 0; mf < 4; ++mf) {
        const int r_lo = m0 + wm * 64 + mf * 16 + g;
#pragma unroll
        for (int nf = 0; nf < 8; ++nf) {
            const int col = n0 + wn * 64 + nf * 8 + 2 * t;
            const float b0 = bias[col], b1 = bias[col + 1];
            float v00 = acc[mf][nf][0] + b0, v01 = acc[mf][nf][1] + b1;
            float v10 = acc[mf][nf][2] + b0, v11 = acc[mf][nf][3] + b1;
            if (MODE == 0) {
                const int which = col >> 10;
                const int ci = col & 1023;
                const int hh = ci >> 6;
                const int dd = ci & 63;
                __half* dst = (which == 0) ? g_q16 : ((which == 1) ? g_k16 : g_v16);
                const int b_lo = r_lo >> 11, t_lo = r_lo & 2047;
                const int r_hi = r_lo + 8;
                const int b_hi = r_hi >> 11, t_hi = r_hi & 2047;
                size_t off0 = (((size_t)b_lo * HH + hh) * TT + t_lo) * DD + dd;
                size_t off1 = (((size_t)b_hi * HH + hh) * TT + t_hi) * DD + dd;
                *(uint32_t*)(dst + off0) = pack2h(v00, v01);
                *(uint32_t*)(dst + off1) = pack2h(v10, v11);
            } else {
                *(float2*)(Out + (size_t)r_lo * Ndim + col) = float2{v00, v01};
                *(float2*)(Out + (size_t)(r_lo + 8) * Ndim + col) = float2{v10, v11};
            }
        }
    }
}

// ---------------------------------------------------------------------------
// Tensor-core flash attention: all-fp16 MMAs, 128-thread CTAs (64 q-rows),
// MUFU.EX2 exponentials, 3-stage KV cp.async pipeline (one sync per iter).
// SMEM: Q @0 (8KB); KV buffers @8192 + (kt%3)*16384: K@0 V@8192.
// ---------------------------------------------------------------------------
__global__ __launch_bounds__(128, 3) void attn_mma_kernel(const float* __restrict__ temp)
{
    extern __shared__ __align__(1024) char smem[];
    const uint32_t sb = smem_to_u32(smem);
    const int tid = threadIdx.x;
    const int lane = tid & 31;
    const int wid = tid >> 5;          // 0..3
    const int bh = blockIdx.y;
    const int qt = (int)gridDim.x - 1 - blockIdx.x;   // heavy tiles first
    const int b = bh >> 4;
    const int h = bh & 15;

    const float qscale = 0.125f * (1.0f / temp[0]) * 1.44269504088896340736f;
    const float slope = fexp2(-0.5f * (float)(h + 1)) * 1.44269504088896340736f;

    const int q8 = lane >> 3;
    const int iq = lane & 7;
    const int rowoff = ((q8 & 1) << 3) + iq;
    const int khalf = q8 >> 1;
    const int g = lane >> 2, t = lane & 3;

    const char* gQ = (const char*)g_q16 + ((size_t)bh * TT + qt * 64) * 128;
    const char* gK = (const char*)g_k16 + (size_t)bh * TT * 128;
    const char* gV = (const char*)g_v16 + (size_t)bh * TT * 128;

    const int nkt = qt + 1;   // 64-key tiles (causal)

    // stage Q (8KB: 64 rows x 128B)
#pragma unroll
    for (int i = 0; i < 4; ++i) {
        const int idx = tid + i * 128;
        const int row = idx >> 3;
        const int ch = idx & 7;
        const uint32_t soff = row * 128 + ((ch ^ (row & 7)) << 4);
        cpasync16(sb + soff, gQ + (size_t)row * 128 + ch * 16);
    }
    CP_COMMIT();

    auto issue_kv = [&](int kt) {
        const uint32_t tb = sb + 8192 + (uint32_t)(kt % 3) * 16384;
        const size_t kbase = (size_t)kt * 64 * 128;
#pragma unroll
        for (int i = 0; i < 4; ++i) {
            const int idx = tid + i * 128;
            const int row = idx >> 3;
            const int ch = idx & 7;
            const uint32_t soff = row * 128 + ((ch ^ (row & 7)) << 4);
            const size_t goff = kbase + (size_t)row * 128 + ch * 16;
            cpasync16(tb + 0    + soff, gK + goff);
            cpasync16(tb + 8192 + soff, gV + goff);
        }
        CP_COMMIT();
    };

    issue_kv(0);
    if (nkt > 1) { issue_kv(1); CP_WAIT(2); }  // Q complete (kv0,kv1 in flight)
    else         { CP_WAIT(1); }               // Q complete (kv0 in flight)
    __syncthreads();

    // Q fragments resident (4 k16-steps; warp owns rows wid*16..wid*16+15)
    uint32_t qf[4][4];
#pragma unroll
    for (int ks = 0; ks < 4; ++ks) {
        const int row = wid * 16 + rowoff;
        const int cch = ks * 2 + khalf;
        const uint32_t off = row * 128 + ((cch ^ (row & 7)) << 4);
        LDSM_X4(qf[ks], sb + off);
    }

    float oacc[8][4];
#pragma unroll
    for (int nd = 0; nd < 8; ++nd)
#pragma unroll
        for (int e = 0; e < 4; ++e) oacc[nd][e] = 0.f;
    float m0 = -1e30f, m1 = -1e30f, l0 = 0.f, l1 = 0.f;

    const int qrow0 = qt * 64 + wid * 16 + g;
    const int qrow1 = qrow0 + 8;

    for (int kt = 0; kt < nkt; ++kt) {
        if (kt + 1 < nkt) CP_WAIT(1);   // kv(kt) resident, kv(kt+1) in flight
        else              CP_WAIT(0);
        __syncthreads();                 // all warps done with buffer (kt+2)%3
        if (kt + 2 < nkt) issue_kv(kt + 2);

        const uint32_t tb = sb + 8192 + (uint32_t)(kt % 3) * 16384;

        // ---- S = Q K^T (fp16) ----
        float sacc[8][4];
#pragma unroll
        for (int nf = 0; nf < 8; ++nf)
#pragma unroll
            for (int e = 0; e < 4; ++e) sacc[nf][e] = 0.f;

#pragma unroll
        for (int ks = 0; ks < 4; ++ks) {
            const int cch = ks * 2 + khalf;
#pragma unroll
            for (int np = 0; np < 4; ++np) {
                const int row = np * 16 + rowoff;
                const uint32_t off = row * 128 + ((cch ^ (row & 7)) << 4);
                uint32_t r[4];
                LDSM_X4(r, tb + off);
                MMA_FP16(sacc[2 * np],     qf[ks], r[0], r[2]);
                MMA_FP16(sacc[2 * np + 1], qf[ks], r[1], r[3]);
            }
        }

        // ---- softmax (online) ----
        const bool maskt = (kt == qt);
        float mx0 = -1e30f, mx1 = -1e30f;
#pragma unroll
        for (int nf = 0; nf < 8; ++nf) {
            const int key = kt * 64 + nf * 8 + 2 * t;
            float s0 = fmaf(sacc[nf][0], qscale, slope * (float)(key - qrow0));
            float s1 = fmaf(sacc[nf][1], qscale, slope * (float)(key + 1 - qrow0));
            float s2 = fmaf(sacc[nf][2], qscale, slope * (float)(key - qrow1));
            float s3 = fmaf(sacc[nf][3], qscale, slope * (float)(key + 1 - qrow1));
            if (maskt) {
                if (key > qrow0) s0 = -1e30f;
                if (key + 1 > qrow0) s1 = -1e30f;
                if (key > qrow1) s2 = -1e30f;
                if (key + 1 > qrow1) s3 = -1e30f;
            }
            sacc[nf][0] = s0; sacc[nf][1] = s1; sacc[nf][2] = s2; sacc[nf][3] = s3;
            mx0 = fmaxf(mx0, fmaxf(s0, s1));
            mx1 = fmaxf(mx1, fmaxf(s2, s3));
        }
        mx0 = fmaxf(mx0, __shfl_xor_sync(0xFFFFFFFFu, mx0, 1));
        mx0 = fmaxf(mx0, __shfl_xor_sync(0xFFFFFFFFu, mx0, 2));
        mx1 = fmaxf(mx1, __shfl_xor_sync(0xFFFFFFFFu, mx1, 1));
        mx1 = fmaxf(mx1, __shfl_xor_sync(0xFFFFFFFFu, mx1, 2));

        const float mn0 = fmaxf(m0, mx0);
        const float mn1 = fmaxf(m1, mx1);
        const float a0 = fexp2(m0 - mn0);
        const float a1 = fexp2(m1 - mn1);
        m0 = mn0; m1 = mn1;
        l0 *= a0; l1 *= a1;
#pragma unroll
        for (int nd = 0; nd < 8; ++nd) {
            oacc[nd][0] *= a0; oacc[nd][1] *= a0;
            oacc[nd][2] *= a1; oacc[nd][3] *= a1;
        }

        float rs0 = 0.f, rs1 = 0.f;
#pragma unroll
        for (int nf = 0; nf < 8; ++nf) {
            float p0 = fexp2(sacc[nf][0] - m0);
            float p1 = fexp2(sacc[nf][1] - m0);
            float p2 = fexp2(sacc[nf][2] - m1);
            float p3 = fexp2(sacc[nf][3] - m1);
            rs0 += p0 + p1; rs1 += p2 + p3;
            sacc[nf][0] = p0; sacc[nf][1] = p1; sacc[nf][2] = p2; sacc[nf][3] = p3;
        }
        rs0 += __shfl_xor_sync(0xFFFFFFFFu, rs0, 1);
        rs0 += __shfl_xor_sync(0xFFFFFFFFu, rs0, 2);
        rs1 += __shfl_xor_sync(0xFFFFFFFFu, rs1, 1);
        rs1 += __shfl_xor_sync(0xFFFFFFFFu, rs1, 2);
        l0 += rs0; l1 += rs1;

        // ---- pack P to fp16 A-frags ----
        uint32_t pa[4][4];
#pragma unroll
        for (int jp = 0; jp < 4; ++jp) {
            const int j0 = 2 * jp, j1 = 2 * jp + 1;
            pa[jp][0] = pack2h(sacc[j0][0], sacc[j0][1]);
            pa[jp][1] = pack2h(sacc[j0][2], sacc[j0][3]);
            pa[jp][2] = pack2h(sacc[j1][0], sacc[j1][1]);
            pa[jp][3] = pack2h(sacc[j1][2], sacc[j1][3]);
        }

        // ---- O += P V (fp16) ----
#pragma unroll
        for (int jp = 0; jp < 4; ++jp) {
            uint32_t vb[8][2];
#pragma unroll
            for (int p = 0; p < 4; ++p) {
                const int row = jp * 16 + rowoff;
                const int cch = 2 * p + khalf;
                const uint32_t off = row * 128 + ((cch ^ (row & 7)) << 4);
                uint32_t r[4];
                LDSM_X4_T(r, tb + 8192 + off);
                vb[2 * p][0] = r[0]; vb[2 * p][1] = r[1];
                vb[2 * p + 1][0] = r[2]; vb[2 * p + 1][1] = r[3];
            }
#pragma unroll
            for (int nd = 0; nd < 8; ++nd)
                MMA_FP16(oacc[nd], pa[jp], vb[nd][0], vb[nd][1]);
        }
        // (no trailing sync: next iteration's top sync protects buffer reuse)
    }

    // epilogue: O /= l; write fp16 A operand for proj GEMM
    const float il0 = 1.0f / l0;
    const float il1 = 1.0f / l1;
    const size_t r0off = (size_t)(b * TT + qrow0) * CC + h * 64;
    const size_t r1off = (size_t)(b * TT + qrow1) * CC + h * 64;
#pragma unroll
    for (int nd = 0; nd < 8; ++nd) {
        const int cd = nd * 8 + 2 * t;
        *(uint32_t*)(g_a16 + r0off + cd) = pack2h(oacc[nd][0] * il0, oacc[nd][1] * il0);
        *(uint32_t*)(g_a16 + r1off + cd) = pack2h(oacc[nd][2] * il1, oacc[nd][3] * il1);
    }
}

// ---------------------------------------------------------------------------
// Harness entry
// ---------------------------------------------------------------------------
extern "C" void kernel_launch(void* const* d_in, const int* in_sizes, int n_in,
                              void* d_out, int out_size)
{
    const float* x      = (const float*)d_in[0];
    const float* W_attn = (const float*)d_in[1];
    const float* b_attn = (const float*)d_in[2];
    const float* W_proj = (const float*)d_in[3];
    const float* b_proj = (const float*)d_in[4];
    const float* temp   = (const float*)d_in[5];
    float* out = (float*)d_out;

    const int GEMM_SMEM = 3 * 16384;            // 49152
    const int ATTN_SMEM = 8192 + 3 * 16384;     // 57344 (3 CTAs/SM)
    cudaFuncSetAttribute(hmma_gemm_kernel<3 * CC, 0>,
                         cudaFuncAttributeMaxDynamicSharedMemorySize, GEMM_SMEM);
    cudaFuncSetAttribute(hmma_gemm_kernel<CC, 1>,
                         cudaFuncAttributeMaxDynamicSharedMemorySize, GEMM_SMEM);
    cudaFuncSetAttribute(attn_mma_kernel,
                         cudaFuncAttributeMaxDynamicSharedMemorySize, ATTN_SMEM);

    // 0) fused prep: x convert + both weight transposes in ONE launch
    prep_kernel<<<8192, 256>>>(x, W_attn, W_proj);

    // 1) QKV = x @ W_attn + b_attn  (fp16 HMMA, 4-warp 64x64 warp tiles)
    hmma_gemm_kernel<3 * CC, 0><<<dim3(3 * CC / 128, MM / 128), 128, GEMM_SMEM>>>(
        b_attn, nullptr);

    // 2) tensor-core causal ALiBi attention (3-stage KV pipeline)
    attn_mma_kernel<<<dim3(TT / 64, BB * HH), 128, ATTN_SMEM>>>(temp);

    // 3) out = att @ W_proj + b_proj  (fp16 HMMA)
    hmma_gemm_kernel<CC, 1><<<dim3(CC / 128, MM / 128), 128, GEMM_SMEM>>>(
        b_proj, out);
}